// round 3
// baseline (speedup 1.0000x reference)
#include <cuda_runtime.h>
#include <cstdint>
#include <math.h>

// ---------------------------------------------------------------------------
// FNetBlock: out = L * X * R^T per 256x256 slice (1024 slices), where
// L = M(pi3)*M(pi1), R = M(pi2)*M(pi0),
// M(p)[k][j] = 2*cos(k*(PI*(2j+1) + s_j*(p-PI))/512), s_j = +1 even j, -1 odd j.
// pi_i are Monte-Carlo estimates using JAX threefry2x32, reproduced exactly.
// ---------------------------------------------------------------------------

__device__ int   g_counts[4];
__device__ float g_M[4][256 * 256];
__device__ float g_L[256 * 256];
__device__ float g_Rt[256 * 256];          // R^T, row-major: Rt[k][j] = R[j][k]
__device__ float g_T[16 * 64 * 256 * 256]; // intermediate T = X * R^T (268 MB)

// ---------------- Threefry-2x32, 20 rounds (JAX-compatible) ----------------
__device__ __forceinline__ void tf2x32(uint32_t k0, uint32_t k1,
                                       uint32_t x0, uint32_t x1,
                                       uint32_t& o0, uint32_t& o1) {
    uint32_t k2 = k0 ^ k1 ^ 0x1BD11BDAu;
#define TFR(r) { x0 += x1; x1 = __funnelshift_l(x1, x1, (r)); x1 ^= x0; }
    x0 += k0; x1 += k1;
    TFR(13) TFR(15) TFR(26) TFR(6)
    x0 += k1; x1 += k2 + 1u;
    TFR(17) TFR(29) TFR(16) TFR(24)
    x0 += k2; x1 += k0 + 2u;
    TFR(13) TFR(15) TFR(26) TFR(6)
    x0 += k0; x1 += k1 + 3u;
    TFR(17) TFR(29) TFR(16) TFR(24)
    x0 += k1; x1 += k2 + 4u;
    TFR(13) TFR(15) TFR(26) TFR(6)
    x0 += k2; x1 += k0 + 5u;
#undef TFR
    o0 = x0; o1 = x1;
}

__global__ void zero_counts_kernel() {
    if (threadIdx.x < 4) g_counts[threadIdx.x] = 0;
}

// Each pi uses 2^24 threefry counter blocks: block c has x=(c, c+2^24),
// producing flat bits at positions c (out0) and c+2^24 (out1).
// Sample i = (flat[2i], flat[2i+1]). A counter PAIR (2t, 2t+1) yields
// sample t (from out0s) and sample 2^23+t (from out1s).
#define PI_ITER 8
#define PI_TPB  256
#define PI_BPP  4096  // (2^23 pairs) / (256 * 8)

__global__ __launch_bounds__(PI_TPB) void pi_kernel() {
    int p   = blockIdx.x >> 12;      // blockIdx.x / PI_BPP
    int blk = blockIdx.x & (PI_BPP - 1);

    uint32_t k0, k1;                 // fold_in(key(42), p)
    tf2x32(0u, 42u, 0u, (uint32_t)p, k0, k1);

    int cnt = 0;
#pragma unroll 2
    for (int it = 0; it < PI_ITER; it++) {
        uint32_t t  = (uint32_t)blk * (PI_TPB * PI_ITER) + it * PI_TPB + threadIdx.x;
        uint32_t c0 = 2u * t, c1 = 2u * t + 1u;
        uint32_t a0, a1, b0, b1;
        tf2x32(k0, k1, c0, c0 + 16777216u, a0, a1);
        tf2x32(k0, k1, c1, c1 + 16777216u, b0, b1);
        float ua0 = __uint_as_float((a0 >> 9) | 0x3f800000u) - 1.0f;
        float ub0 = __uint_as_float((b0 >> 9) | 0x3f800000u) - 1.0f;
        float ua1 = __uint_as_float((a1 >> 9) | 0x3f800000u) - 1.0f;
        float ub1 = __uint_as_float((b1 >> 9) | 0x3f800000u) - 1.0f;
        cnt += (ua0 * ua0 + ub0 * ub0 < 1.0f) ? 1 : 0;
        cnt += (ua1 * ua1 + ub1 * ub1 < 1.0f) ? 1 : 0;
    }
    // warp + block reduction, one atomic per block
    for (int off = 16; off; off >>= 1)
        cnt += __shfl_down_sync(0xffffffffu, cnt, off);
    __shared__ int ws[PI_TPB / 32];
    if ((threadIdx.x & 31) == 0) ws[threadIdx.x >> 5] = cnt;
    __syncthreads();
    if (threadIdx.x == 0) {
        int s = 0;
#pragma unroll
        for (int i = 0; i < PI_TPB / 32; i++) s += ws[i];
        atomicAdd(&g_counts[p], s);
    }
}

// ---------------- Build the 4 effective DCT matrices -----------------------
__global__ void build_M_kernel() {
    int p = blockIdx.y;       // pi index 0..3
    int k = blockIdx.x;       // row 0..255
    int j = threadIdx.x;      // col 0..255
    float  pv    = 4.0f * (float)g_counts[p] / 16777216.0f; // exact fp32
    double delta = (double)pv - M_PI;
    double sgn   = (j & 1) ? -1.0 : 1.0;
    double ang   = (double)k * (M_PI * (double)(2 * j + 1) + sgn * delta) / 512.0;
    g_M[p][k * 256 + j] = (float)(2.0 * cos(ang));
}

// L = M3*M1 ; R = M2*M0 stored transposed
__global__ void compose_kernel() {
    int j = blockIdx.x * 16 + threadIdx.x;
    int i = blockIdx.y * 16 + threadIdx.y;
    if (blockIdx.z == 0) {
        float s = 0.f;
#pragma unroll 8
        for (int t = 0; t < 256; t++)
            s += g_M[3][i * 256 + t] * g_M[1][t * 256 + j];
        g_L[i * 256 + j] = s;
    } else {
        float s = 0.f;
#pragma unroll 8
        for (int t = 0; t < 256; t++)
            s += g_M[2][i * 256 + t] * g_M[0][t * 256 + j];
        g_Rt[j * 256 + i] = s;   // store R transposed
    }
}

// ---------------- 128x128x8 fp32 GEMM, 8x8 microtile, double-buffered ------
// C = A * B with K = 256, all leading dims = 256, A rows tiled by blockIdx.y,
// B cols tiled by blockIdx.x, batch via blockIdx.z with given strides.
__global__ __launch_bounds__(256, 2) void sgemm_kernel(
    const float* __restrict__ Abase, const float* __restrict__ Bbase,
    float* __restrict__ Cbase,
    long long aStride, long long bStride, long long cStride) {
    const int K = 256, LD = 256;
    __shared__ float As[2][8][128];
    __shared__ float Bs[2][8][128];

    long long bb = blockIdx.z;
    const float* A = Abase + bb * aStride + (long long)blockIdx.y * 128 * K;
    const float* B = Bbase + bb * bStride + blockIdx.x * 128;
    float*       C = Cbase + bb * cStride + (long long)blockIdx.y * 128 * LD + blockIdx.x * 128;

    int tid  = threadIdx.x;
    int arow = tid >> 1;            // 0..127
    int acol = (tid & 1) << 2;      // 0 or 4
    int brow = tid >> 5;            // 0..7
    int bcol = (tid & 31) << 2;     // 0..124
    int tm   = (tid >> 4) << 3;     // 0..120
    int tn   = (tid & 15) << 3;     // 0..120

    float4 ag = *(const float4*)(A + arow * K + acol);
    float4 bg = *(const float4*)(B + brow * LD + bcol);

    float acc[8][8];
#pragma unroll
    for (int i = 0; i < 8; i++)
#pragma unroll
        for (int j = 0; j < 8; j++) acc[i][j] = 0.f;

    int buf = 0;
#pragma unroll 1
    for (int kt = 0; kt < 32; kt++) {
        As[buf][acol + 0][arow] = ag.x;
        As[buf][acol + 1][arow] = ag.y;
        As[buf][acol + 2][arow] = ag.z;
        As[buf][acol + 3][arow] = ag.w;
        *(float4*)&Bs[buf][brow][bcol] = bg;
        __syncthreads();
        if (kt < 31) {
            ag = *(const float4*)(A + arow * K + (kt + 1) * 8 + acol);
            bg = *(const float4*)(B + ((kt + 1) * 8 + brow) * LD + bcol);
        }
#pragma unroll
        for (int k = 0; k < 8; k++) {
            float4 a0 = *(const float4*)&As[buf][k][tm];
            float4 a1 = *(const float4*)&As[buf][k][tm + 4];
            float4 b0 = *(const float4*)&Bs[buf][k][tn];
            float4 b1 = *(const float4*)&Bs[buf][k][tn + 4];
            float av[8] = {a0.x, a0.y, a0.z, a0.w, a1.x, a1.y, a1.z, a1.w};
            float bv[8] = {b0.x, b0.y, b0.z, b0.w, b1.x, b1.y, b1.z, b1.w};
#pragma unroll
            for (int i = 0; i < 8; i++)
#pragma unroll
                for (int j = 0; j < 8; j++)
                    acc[i][j] += av[i] * bv[j];
        }
        buf ^= 1;
    }

#pragma unroll
    for (int i = 0; i < 8; i++) {
        *(float4*)(C + (tm + i) * LD + tn)     = make_float4(acc[i][0], acc[i][1], acc[i][2], acc[i][3]);
        *(float4*)(C + (tm + i) * LD + tn + 4) = make_float4(acc[i][4], acc[i][5], acc[i][6], acc[i][7]);
    }
}

// ---------------------------------------------------------------------------
extern "C" void kernel_launch(void* const* d_in, const int* in_sizes, int n_in,
                              void* d_out, int out_size) {
    const float* x = (const float*)d_in[0];
    if (n_in > 1 && in_sizes[0] == 1) x = (const float*)d_in[1];  // robustness
    float* out = (float*)d_out;

    float* pT;  cudaGetSymbolAddress((void**)&pT,  g_T);
    float* pL;  cudaGetSymbolAddress((void**)&pL,  g_L);
    float* pRt; cudaGetSymbolAddress((void**)&pRt, g_Rt);

    zero_counts_kernel<<<1, 32>>>();
    pi_kernel<<<4 * PI_BPP, PI_TPB>>>();
    build_M_kernel<<<dim3(256, 4, 1), 256>>>();
    compose_kernel<<<dim3(16, 16, 2), dim3(16, 16, 1)>>>();

    // Stage 1: T = X * R^T  (flat GEMM: M = 16*64*256 = 262,144 rows, N = K = 256)
    sgemm_kernel<<<dim3(2, 2048, 1), 256>>>(x, pRt, pT, 0LL, 0LL, 0LL);

    // Stage 2: out[b] = L * T[b]  (1024 batched 256x256x256 GEMMs)
    sgemm_kernel<<<dim3(2, 2, 1024), 256>>>(pL, pT, out, 0LL, 65536LL, 65536LL);
}

// round 4
// speedup vs baseline: 1.0006x; 1.0006x over previous
#include <cuda_runtime.h>
#include <cstdint>
#include <math.h>

// ---------------------------------------------------------------------------
// FNetBlock: out = L * X * R^T per 256x256 slice (1024 slices), where
// L = M(pi3)*M(pi1), R = M(pi2)*M(pi0),
// M(p)[k][j] = 2*cos(k*(PI*(2j+1) + s_j*(p-PI))/512), s_j = +1 even j, -1 odd j.
// pi_i are Monte-Carlo estimates using JAX threefry2x32, reproduced exactly.
// ---------------------------------------------------------------------------

__device__ int   g_counts[4];
__device__ float g_M[4][256 * 256];
__device__ float g_L[256 * 256];
__device__ float g_Rt[256 * 256];          // R^T, row-major: Rt[k][j] = R[j][k]
__device__ float g_T[16 * 64 * 256 * 256]; // intermediate T = X * R^T (268 MB)

// ---------------- Threefry-2x32, 20 rounds (JAX-compatible) ----------------
__device__ __forceinline__ void tf2x32(uint32_t k0, uint32_t k1,
                                       uint32_t x0, uint32_t x1,
                                       uint32_t& o0, uint32_t& o1) {
    uint32_t k2 = k0 ^ k1 ^ 0x1BD11BDAu;
#define TFR(r) { x0 += x1; x1 = __funnelshift_l(x1, x1, (r)); x1 ^= x0; }
    x0 += k0; x1 += k1;
    TFR(13) TFR(15) TFR(26) TFR(6)
    x0 += k1; x1 += k2 + 1u;
    TFR(17) TFR(29) TFR(16) TFR(24)
    x0 += k2; x1 += k0 + 2u;
    TFR(13) TFR(15) TFR(26) TFR(6)
    x0 += k0; x1 += k1 + 3u;
    TFR(17) TFR(29) TFR(16) TFR(24)
    x0 += k1; x1 += k2 + 4u;
    TFR(13) TFR(15) TFR(26) TFR(6)
    x0 += k2; x1 += k0 + 5u;
#undef TFR
    o0 = x0; o1 = x1;
}

__global__ void zero_counts_kernel() {
    if (threadIdx.x < 4) g_counts[threadIdx.x] = 0;
}

// Each pi uses 2^24 threefry counter blocks: block c has x=(c, c+2^24),
// producing flat bits at positions c (out0) and c+2^24 (out1).
// Sample i = (flat[2i], flat[2i+1]). A counter PAIR (2t, 2t+1) yields
// sample t (from out0s) and sample 2^23+t (from out1s).
#define PI_ITER 8
#define PI_TPB  256
#define PI_BPP  4096  // (2^23 pairs) / (256 * 8)

__global__ __launch_bounds__(PI_TPB) void pi_kernel() {
    int p   = blockIdx.x >> 12;      // blockIdx.x / PI_BPP
    int blk = blockIdx.x & (PI_BPP - 1);

    uint32_t k0, k1;                 // fold_in(key(42), p)
    tf2x32(0u, 42u, 0u, (uint32_t)p, k0, k1);

    int cnt = 0;
#pragma unroll 2
    for (int it = 0; it < PI_ITER; it++) {
        uint32_t t  = (uint32_t)blk * (PI_TPB * PI_ITER) + it * PI_TPB + threadIdx.x;
        uint32_t c0 = 2u * t, c1 = 2u * t + 1u;
        uint32_t a0, a1, b0, b1;
        tf2x32(k0, k1, c0, c0 + 16777216u, a0, a1);
        tf2x32(k0, k1, c1, c1 + 16777216u, b0, b1);
        float ua0 = __uint_as_float((a0 >> 9) | 0x3f800000u) - 1.0f;
        float ub0 = __uint_as_float((b0 >> 9) | 0x3f800000u) - 1.0f;
        float ua1 = __uint_as_float((a1 >> 9) | 0x3f800000u) - 1.0f;
        float ub1 = __uint_as_float((b1 >> 9) | 0x3f800000u) - 1.0f;
        cnt += (ua0 * ua0 + ub0 * ub0 < 1.0f) ? 1 : 0;
        cnt += (ua1 * ua1 + ub1 * ub1 < 1.0f) ? 1 : 0;
    }
    // warp + block reduction, one atomic per block
    for (int off = 16; off; off >>= 1)
        cnt += __shfl_down_sync(0xffffffffu, cnt, off);
    __shared__ int ws[PI_TPB / 32];
    if ((threadIdx.x & 31) == 0) ws[threadIdx.x >> 5] = cnt;
    __syncthreads();
    if (threadIdx.x == 0) {
        int s = 0;
#pragma unroll
        for (int i = 0; i < PI_TPB / 32; i++) s += ws[i];
        atomicAdd(&g_counts[p], s);
    }
}

// ---------------- Build the 4 effective DCT matrices -----------------------
__global__ void build_M_kernel() {
    int p = blockIdx.y;       // pi index 0..3
    int k = blockIdx.x;       // row 0..255
    int j = threadIdx.x;      // col 0..255
    float  pv    = 4.0f * (float)g_counts[p] / 16777216.0f; // exact fp32
    double delta = (double)pv - M_PI;
    double sgn   = (j & 1) ? -1.0 : 1.0;
    double ang   = (double)k * (M_PI * (double)(2 * j + 1) + sgn * delta) / 512.0;
    g_M[p][k * 256 + j] = (float)(2.0 * cos(ang));
}

// L = M3*M1 ; R = M2*M0 stored transposed
__global__ void compose_kernel() {
    int j = blockIdx.x * 16 + threadIdx.x;
    int i = blockIdx.y * 16 + threadIdx.y;
    if (blockIdx.z == 0) {
        float s = 0.f;
#pragma unroll 8
        for (int t = 0; t < 256; t++)
            s += g_M[3][i * 256 + t] * g_M[1][t * 256 + j];
        g_L[i * 256 + j] = s;
    } else {
        float s = 0.f;
#pragma unroll 8
        for (int t = 0; t < 256; t++)
            s += g_M[2][i * 256 + t] * g_M[0][t * 256 + j];
        g_Rt[j * 256 + i] = s;   // store R transposed
    }
}

// ---------------- 128x128x8 fp32 GEMM, 8x8 microtile, double-buffered ------
// C = A * B with K = 256, all leading dims = 256, A rows tiled by blockIdx.y,
// B cols tiled by blockIdx.x, batch via blockIdx.z with given strides.
__global__ __launch_bounds__(256, 2) void sgemm_kernel(
    const float* __restrict__ Abase, const float* __restrict__ Bbase,
    float* __restrict__ Cbase,
    long long aStride, long long bStride, long long cStride) {
    const int K = 256, LD = 256;
    __shared__ float As[2][8][128];
    __shared__ float Bs[2][8][128];

    long long bb = blockIdx.z;
    const float* A = Abase + bb * aStride + (long long)blockIdx.y * 128 * K;
    const float* B = Bbase + bb * bStride + blockIdx.x * 128;
    float*       C = Cbase + bb * cStride + (long long)blockIdx.y * 128 * LD + blockIdx.x * 128;

    int tid  = threadIdx.x;
    int arow = tid >> 1;            // 0..127
    int acol = (tid & 1) << 2;      // 0 or 4
    int brow = tid >> 5;            // 0..7
    int bcol = (tid & 31) << 2;     // 0..124
    int tm   = (tid >> 4) << 3;     // 0..120
    int tn   = (tid & 15) << 3;     // 0..120

    float4 ag = *(const float4*)(A + arow * K + acol);
    float4 bg = *(const float4*)(B + brow * LD + bcol);

    float acc[8][8];
#pragma unroll
    for (int i = 0; i < 8; i++)
#pragma unroll
        for (int j = 0; j < 8; j++) acc[i][j] = 0.f;

    int buf = 0;
#pragma unroll 1
    for (int kt = 0; kt < 32; kt++) {
        As[buf][acol + 0][arow] = ag.x;
        As[buf][acol + 1][arow] = ag.y;
        As[buf][acol + 2][arow] = ag.z;
        As[buf][acol + 3][arow] = ag.w;
        *(float4*)&Bs[buf][brow][bcol] = bg;
        __syncthreads();
        if (kt < 31) {
            ag = *(const float4*)(A + arow * K + (kt + 1) * 8 + acol);
            bg = *(const float4*)(B + ((kt + 1) * 8 + brow) * LD + bcol);
        }
#pragma unroll
        for (int k = 0; k < 8; k++) {
            float4 a0 = *(const float4*)&As[buf][k][tm];
            float4 a1 = *(const float4*)&As[buf][k][tm + 4];
            float4 b0 = *(const float4*)&Bs[buf][k][tn];
            float4 b1 = *(const float4*)&Bs[buf][k][tn + 4];
            float av[8] = {a0.x, a0.y, a0.z, a0.w, a1.x, a1.y, a1.z, a1.w};
            float bv[8] = {b0.x, b0.y, b0.z, b0.w, b1.x, b1.y, b1.z, b1.w};
#pragma unroll
            for (int i = 0; i < 8; i++)
#pragma unroll
                for (int j = 0; j < 8; j++)
                    acc[i][j] += av[i] * bv[j];
        }
        buf ^= 1;
    }

#pragma unroll
    for (int i = 0; i < 8; i++) {
        *(float4*)(C + (tm + i) * LD + tn)     = make_float4(acc[i][0], acc[i][1], acc[i][2], acc[i][3]);
        *(float4*)(C + (tm + i) * LD + tn + 4) = make_float4(acc[i][4], acc[i][5], acc[i][6], acc[i][7]);
    }
}

// ---------------------------------------------------------------------------
extern "C" void kernel_launch(void* const* d_in, const int* in_sizes, int n_in,
                              void* d_out, int out_size) {
    const float* x = (const float*)d_in[0];
    if (n_in > 1 && in_sizes[0] == 1) x = (const float*)d_in[1];  // robustness
    float* out = (float*)d_out;

    float* pT;  cudaGetSymbolAddress((void**)&pT,  g_T);
    float* pL;  cudaGetSymbolAddress((void**)&pL,  g_L);
    float* pRt; cudaGetSymbolAddress((void**)&pRt, g_Rt);

    zero_counts_kernel<<<1, 32>>>();
    pi_kernel<<<4 * PI_BPP, PI_TPB>>>();
    build_M_kernel<<<dim3(256, 4, 1), 256>>>();
    compose_kernel<<<dim3(16, 16, 2), dim3(16, 16, 1)>>>();

    // Stage 1: T = X * R^T  (flat GEMM: M = 16*64*256 = 262,144 rows, N = K = 256)
    sgemm_kernel<<<dim3(2, 2048, 1), 256>>>(x, pRt, pT, 0LL, 0LL, 0LL);

    // Stage 2: out[b] = L * T[b]  (1024 batched 256x256x256 GEMMs)
    sgemm_kernel<<<dim3(2, 2, 1024), 256>>>(pL, pT, out, 0LL, 65536LL, 65536LL);
}

// round 9
// speedup vs baseline: 1.2631x; 1.2624x over previous
#include <cuda_runtime.h>
#include <cuda_bf16.h>
#include <cstdint>
#include <math.h>

// ---------------------------------------------------------------------------
// FNetBlock: out = L * X * R^T per 256x256 slice (1024 slices), where
// L = M(pi3)*M(pi1), R = M(pi2)*M(pi0),
// M(p)[k][j] = 2*cos(k*(PI*(2j+1) + s_j*(p-PI))/512), s_j = +1 even j, -1 odd j.
// pi_i are Monte-Carlo estimates via JAX threefry2x32 reproduced exactly.
//
// GEMMs via mma.sync (HMMA, bf16 3-term split). No 'a'-suffix PTX features.
//   Stage 1: T'[n][m] = sum_k R[n,k] X[m,k]     (A=R, B=X, both k-contiguous)
//   Stage 2: out[i][n] = sum_m L[i,m] T'[n,m]   (A=L, B=T', both k-contiguous)
// T' stored packed bf16 hi|lo<<16 per element (uint32).
// ---------------------------------------------------------------------------

__device__ int            g_counts[4];
__device__ float          g_M[4][65536];
__device__ __nv_bfloat16  g_Lhi[65536], g_Llo[65536];
__device__ __nv_bfloat16  g_Rhi[65536], g_Rlo[65536];
__device__ uint32_t       g_Tp[67108864];   // 268 MB packed T'

// ---------------- Threefry-2x32, 20 rounds (JAX-compatible) ----------------
__device__ __forceinline__ void tf2x32(uint32_t k0, uint32_t k1,
                                       uint32_t x0, uint32_t x1,
                                       uint32_t& o0, uint32_t& o1) {
    uint32_t k2 = k0 ^ k1 ^ 0x1BD11BDAu;
#define TFR(r) { x0 += x1; x1 = __funnelshift_l(x1, x1, (r)); x1 ^= x0; }
    x0 += k0; x1 += k1;
    TFR(13) TFR(15) TFR(26) TFR(6)
    x0 += k1; x1 += k2 + 1u;
    TFR(17) TFR(29) TFR(16) TFR(24)
    x0 += k2; x1 += k0 + 2u;
    TFR(13) TFR(15) TFR(26) TFR(6)
    x0 += k0; x1 += k1 + 3u;
    TFR(17) TFR(29) TFR(16) TFR(24)
    x0 += k1; x1 += k2 + 4u;
    TFR(13) TFR(15) TFR(26) TFR(6)
    x0 += k2; x1 += k0 + 5u;
#undef TFR
    o0 = x0; o1 = x1;
}

__global__ void zero_counts_kernel() {
    if (threadIdx.x < 4) g_counts[threadIdx.x] = 0;
}

#define PI_ITER 8
#define PI_TPB  256
#define PI_BPP  4096  // (2^23 pairs) / (256 * 8)

__global__ __launch_bounds__(PI_TPB) void pi_kernel() {
    int p   = blockIdx.x >> 12;
    int blk = blockIdx.x & (PI_BPP - 1);

    uint32_t k0, k1;                 // fold_in(key(42), p)
    tf2x32(0u, 42u, 0u, (uint32_t)p, k0, k1);

    int cnt = 0;
#pragma unroll 2
    for (int it = 0; it < PI_ITER; it++) {
        uint32_t t  = (uint32_t)blk * (PI_TPB * PI_ITER) + it * PI_TPB + threadIdx.x;
        uint32_t c0 = 2u * t, c1 = 2u * t + 1u;
        uint32_t a0, a1, b0, b1;
        tf2x32(k0, k1, c0, c0 + 16777216u, a0, a1);
        tf2x32(k0, k1, c1, c1 + 16777216u, b0, b1);
        float ua0 = __uint_as_float((a0 >> 9) | 0x3f800000u) - 1.0f;
        float ub0 = __uint_as_float((b0 >> 9) | 0x3f800000u) - 1.0f;
        float ua1 = __uint_as_float((a1 >> 9) | 0x3f800000u) - 1.0f;
        float ub1 = __uint_as_float((b1 >> 9) | 0x3f800000u) - 1.0f;
        cnt += (ua0 * ua0 + ub0 * ub0 < 1.0f) ? 1 : 0;
        cnt += (ua1 * ua1 + ub1 * ub1 < 1.0f) ? 1 : 0;
    }
    for (int off = 16; off; off >>= 1)
        cnt += __shfl_down_sync(0xffffffffu, cnt, off);
    __shared__ int ws[PI_TPB / 32];
    if ((threadIdx.x & 31) == 0) ws[threadIdx.x >> 5] = cnt;
    __syncthreads();
    if (threadIdx.x == 0) {
        int s = 0;
#pragma unroll
        for (int i = 0; i < PI_TPB / 32; i++) s += ws[i];
        atomicAdd(&g_counts[p], s);
    }
}

// ---------------- Build the 4 effective DCT matrices -----------------------
__global__ void build_M_kernel() {
    int p = blockIdx.y;
    int k = blockIdx.x;
    int j = threadIdx.x;
    float  pv    = 4.0f * (float)g_counts[p] / 16777216.0f;
    double delta = (double)pv - M_PI;
    double sgn   = (j & 1) ? -1.0 : 1.0;
    double ang   = (double)k * (M_PI * (double)(2 * j + 1) + sgn * delta) / 512.0;
    g_M[p][k * 256 + j] = (float)(2.0 * cos(ang));
}

// L = M3*M1 ; R = M2*M0, written as bf16 hi/lo pairs, natural row-major
__global__ void compose_kernel() {
    int j = blockIdx.x * 16 + threadIdx.x;
    int i = blockIdx.y * 16 + threadIdx.y;
    float s = 0.f;
    if (blockIdx.z == 0) {
#pragma unroll 8
        for (int t = 0; t < 256; t++)
            s += g_M[3][i * 256 + t] * g_M[1][t * 256 + j];
        __nv_bfloat16 h = __float2bfloat16(s);
        g_Lhi[i * 256 + j] = h;
        g_Llo[i * 256 + j] = __float2bfloat16(s - __bfloat162float(h));
    } else {
#pragma unroll 8
        for (int t = 0; t < 256; t++)
            s += g_M[2][i * 256 + t] * g_M[0][t * 256 + j];
        __nv_bfloat16 h = __float2bfloat16(s);
        g_Rhi[i * 256 + j] = h;
        g_Rlo[i * 256 + j] = __float2bfloat16(s - __bfloat162float(h));
    }
}

// ---------------- HMMA GEMM helpers ----------------------------------------
__device__ __forceinline__ uint32_t smem_u32(const void* p) {
    uint32_t a;
    asm("{ .reg .u64 t; cvta.to.shared.u64 t, %1; cvt.u32.u64 %0, t; }"
        : "=r"(a) : "l"(p));
    return a;
}

#define LDSM4(R, A) \
    asm volatile("ldmatrix.sync.aligned.m8n8.x4.shared.b16 {%0,%1,%2,%3}, [%4];" \
                 : "=r"((R)[0]), "=r"((R)[1]), "=r"((R)[2]), "=r"((R)[3]) : "r"(A))

#define MMA(D, A, B0, B1) \
    asm volatile("mma.sync.aligned.m16n8k16.row.col.f32.bf16.bf16.f32 " \
                 "{%0,%1,%2,%3},{%4,%5,%6,%7},{%8,%9},{%0,%1,%2,%3};" \
                 : "+f"((D)[0]), "+f"((D)[1]), "+f"((D)[2]), "+f"((D)[3]) \
                 : "r"((A)[0]), "r"((A)[1]), "r"((A)[2]), "r"((A)[3]), \
                   "r"(B0), "r"(B1))

__device__ __forceinline__ void split2(float x, float y, uint32_t& h, uint32_t& l) {
    __nv_bfloat16 hx = __float2bfloat16(x), hy = __float2bfloat16(y);
    __nv_bfloat16 lx = __float2bfloat16(x - __bfloat162float(hx));
    __nv_bfloat16 ly = __float2bfloat16(y - __bfloat162float(hy));
    h = (uint32_t)__bfloat16_as_ushort(hx) | ((uint32_t)__bfloat16_as_ushort(hy) << 16);
    l = (uint32_t)__bfloat16_as_ushort(lx) | ((uint32_t)__bfloat16_as_ushort(ly) << 16);
}
__device__ __forceinline__ uint32_t packsplit(float v) {
    __nv_bfloat16 h = __float2bfloat16(v);
    __nv_bfloat16 l = __float2bfloat16(v - __bfloat162float(h));
    return (uint32_t)__bfloat16_as_ushort(h) | ((uint32_t)__bfloat16_as_ushort(l) << 16);
}

// smem layout (bytes):
//   A resident: [128 rows][264 bf16] per split (stride 528B, conflict-free LDSM)
//     AH @ 0, AL @ 67584
//   B chunk: [128 rows][40 bf16] (stride 80B), 2 splits x 2 buffers
//     buf b, split s @ 135168 + b*20480 + s*10240
static const int A_STRIDE_B = 528;
static const int B_STRIDE_B = 80;
static const int OFF_AL     = 67584;
static const int OFF_B      = 135168;
static const int SMEM_BYTES = 135168 + 40960;   // 176128

template <int STAGE>
__global__ __launch_bounds__(256) void gemm_kernel(
    const float* __restrict__ X, float* __restrict__ Out) {
    extern __shared__ char smem[];
    uint32_t sbase = smem_u32(smem);
    int tid  = threadIdx.x;
    int warp = tid >> 5, lane = tid & 31;
    int wm = warp & 3, wn = warp >> 2;

    int blk   = blockIdx.x;
    int b     = blk >> 2;
    int rtile = (blk >> 1) & 1;   // rows of output (n for stage1, i for stage2)
    int ctile = blk & 1;          // cols of output (m for stage1, n for stage2)

    // ---- load A (full K) resident: 128 rows x 256 k, hi+lo ----
    {
        const __nv_bfloat16* Agh = (STAGE == 1 ? g_Rhi : g_Lhi) + rtile * 128 * 256;
        const __nv_bfloat16* Agl = (STAGE == 1 ? g_Rlo : g_Llo) + rtile * 128 * 256;
        for (int idx = tid; idx < 128 * 32; idx += 256) {
            int row = idx >> 5, q = idx & 31;          // q: 8-elem group
            *(uint4*)(smem + row * A_STRIDE_B + q * 16) =
                *(const uint4*)(Agh + row * 256 + q * 8);
            *(uint4*)(smem + OFF_AL + row * A_STRIDE_B + q * 16) =
                *(const uint4*)(Agl + row * 256 + q * 8);
        }
    }

    // ---- B prefetch sources ----
    int pr = tid >> 1, pc = (tid & 1) * 16;            // row, 16-elem col group
    const float*    Bg1 = X    + (size_t)b * 65536 + (size_t)(ctile * 128 + pr) * 256 + pc;
    const uint32_t* Bg2 = g_Tp + (size_t)b * 65536 + (size_t)(ctile * 128 + pr) * 256 + pc;

    float4 pf1[4];
    uint4  pf2[4];
    uint32_t hv[8], lv[8];

    // load chunk 0
    if (STAGE == 1) {
#pragma unroll
        for (int q = 0; q < 4; q++) pf1[q] = *(const float4*)(Bg1 + q * 4);
    } else {
#pragma unroll
        for (int q = 0; q < 4; q++) pf2[q] = *(const uint4*)(Bg2 + q * 4);
    }
    // convert + store to buf0
    {
        if (STAGE == 1) {
#pragma unroll
            for (int q = 0; q < 4; q++) {
                split2(pf1[q].x, pf1[q].y, hv[2 * q], lv[2 * q]);
                split2(pf1[q].z, pf1[q].w, hv[2 * q + 1], lv[2 * q + 1]);
            }
        } else {
#pragma unroll
            for (int q = 0; q < 4; q++) {
                uint32_t e[4] = {pf2[q].x, pf2[q].y, pf2[q].z, pf2[q].w};
                hv[2 * q]     = __byte_perm(e[0], e[1], 0x5410);
                lv[2 * q]     = __byte_perm(e[0], e[1], 0x7632);
                hv[2 * q + 1] = __byte_perm(e[2], e[3], 0x5410);
                lv[2 * q + 1] = __byte_perm(e[2], e[3], 0x7632);
            }
        }
        char* dst = smem + OFF_B + pr * B_STRIDE_B + pc * 2;
        *(uint4*)(dst)           = make_uint4(hv[0], hv[1], hv[2], hv[3]);
        *(uint4*)(dst + 16)      = make_uint4(hv[4], hv[5], hv[6], hv[7]);
        *(uint4*)(dst + 10240)      = make_uint4(lv[0], lv[1], lv[2], lv[3]);
        *(uint4*)(dst + 10240 + 16) = make_uint4(lv[4], lv[5], lv[6], lv[7]);
    }
    __syncthreads();

    float acc[2][8][4];
#pragma unroll
    for (int i = 0; i < 2; i++)
#pragma unroll
        for (int j = 0; j < 8; j++)
#pragma unroll
            for (int q = 0; q < 4; q++) acc[i][j][q] = 0.f;

    // ldmatrix base addresses
    uint32_t aH = sbase + (uint32_t)((wm * 32 + (lane & 15)) * A_STRIDE_B + (lane >> 4) * 16);
    uint32_t aL = aH + OFF_AL;
    uint32_t bBase = sbase + OFF_B +
                     (uint32_t)((wn * 64 + (lane & 15)) * B_STRIDE_B + (lane >> 4) * 16);

#pragma unroll 1
    for (int kc = 0; kc < 8; kc++) {
        int buf = kc & 1;
        // issue gmem prefetch of next chunk (latency hidden by MMA below)
        if (kc < 7) {
            if (STAGE == 1) {
#pragma unroll
                for (int q = 0; q < 4; q++)
                    pf1[q] = *(const float4*)(Bg1 + (kc + 1) * 32 + q * 4);
            } else {
#pragma unroll
                for (int q = 0; q < 4; q++)
                    pf2[q] = *(const uint4*)(Bg2 + (kc + 1) * 32 + q * 4);
            }
        }

        uint32_t bBuf = bBase + buf * 20480;
#pragma unroll
        for (int kk = 0; kk < 2; kk++) {
            int kg = kc * 2 + kk;  // global k16 index
            uint32_t ah[2][4], al[2][4], bh[4][4], bl[4][4];
            LDSM4(ah[0], aH + kg * 32);
            LDSM4(ah[1], aH + 16 * A_STRIDE_B + kg * 32);
            LDSM4(al[0], aL + kg * 32);
            LDSM4(al[1], aL + 16 * A_STRIDE_B + kg * 32);
#pragma unroll
            for (int xi = 0; xi < 4; xi++) {
                LDSM4(bh[xi], bBuf + xi * (16 * B_STRIDE_B) + kk * 32);
                LDSM4(bl[xi], bBuf + 10240 + xi * (16 * B_STRIDE_B) + kk * 32);
            }
#pragma unroll
            for (int ms = 0; ms < 2; ms++)
#pragma unroll
                for (int nt = 0; nt < 8; nt++) {
                    int xi = nt >> 1, s = nt & 1;
                    MMA(acc[ms][nt], ah[ms], bh[xi][s], bh[xi][s + 2]);
                    MMA(acc[ms][nt], ah[ms], bl[xi][s], bl[xi][s + 2]);
                    MMA(acc[ms][nt], al[ms], bh[xi][s], bh[xi][s + 2]);
                }
        }

        // store prefetched regs into the other buffer (free since last sync)
        if (kc < 7) {
            if (STAGE == 1) {
#pragma unroll
                for (int q = 0; q < 4; q++) {
                    split2(pf1[q].x, pf1[q].y, hv[2 * q], lv[2 * q]);
                    split2(pf1[q].z, pf1[q].w, hv[2 * q + 1], lv[2 * q + 1]);
                }
            } else {
#pragma unroll
                for (int q = 0; q < 4; q++) {
                    uint32_t e[4] = {pf2[q].x, pf2[q].y, pf2[q].z, pf2[q].w};
                    hv[2 * q]     = __byte_perm(e[0], e[1], 0x5410);
                    lv[2 * q]     = __byte_perm(e[0], e[1], 0x7632);
                    hv[2 * q + 1] = __byte_perm(e[2], e[3], 0x5410);
                    lv[2 * q + 1] = __byte_perm(e[2], e[3], 0x7632);
                }
            }
            char* dst = smem + OFF_B + (buf ^ 1) * 20480 + pr * B_STRIDE_B + pc * 2;
            *(uint4*)(dst)           = make_uint4(hv[0], hv[1], hv[2], hv[3]);
            *(uint4*)(dst + 16)      = make_uint4(hv[4], hv[5], hv[6], hv[7]);
            *(uint4*)(dst + 10240)      = make_uint4(lv[0], lv[1], lv[2], lv[3]);
            *(uint4*)(dst + 10240 + 16) = make_uint4(lv[4], lv[5], lv[6], lv[7]);
        }
        __syncthreads();
    }

    // ---- epilogue ----
    int r0 = wm * 32 + (lane >> 2);
    int cc = wn * 64 + (lane & 3) * 2;
    size_t base = (size_t)b * 65536;
#pragma unroll
    for (int ms = 0; ms < 2; ms++)
#pragma unroll
        for (int nt = 0; nt < 8; nt++) {
            int row0 = rtile * 128 + r0 + ms * 16;
            int col0 = ctile * 128 + cc + nt * 8;
            float* a = acc[ms][nt];
            if (STAGE == 1) {
                uint2 v0 = make_uint2(packsplit(a[0]), packsplit(a[1]));
                uint2 v1 = make_uint2(packsplit(a[2]), packsplit(a[3]));
                *(uint2*)&g_Tp[base + (size_t)row0 * 256 + col0]       = v0;
                *(uint2*)&g_Tp[base + (size_t)(row0 + 8) * 256 + col0] = v1;
            } else {
                *(float2*)&Out[base + (size_t)row0 * 256 + col0]       = make_float2(a[0], a[1]);
                *(float2*)&Out[base + (size_t)(row0 + 8) * 256 + col0] = make_float2(a[2], a[3]);
            }
        }
}

// ---------------------------------------------------------------------------
extern "C" void kernel_launch(void* const* d_in, const int* in_sizes, int n_in,
                              void* d_out, int out_size) {
    const float* x = (const float*)d_in[0];
    if (n_in > 1 && in_sizes[0] == 1) x = (const float*)d_in[1];  // robustness
    float* out = (float*)d_out;

    cudaFuncSetAttribute(gemm_kernel<1>, cudaFuncAttributeMaxDynamicSharedMemorySize, SMEM_BYTES);
    cudaFuncSetAttribute(gemm_kernel<2>, cudaFuncAttributeMaxDynamicSharedMemorySize, SMEM_BYTES);

    zero_counts_kernel<<<1, 32>>>();
    pi_kernel<<<4 * PI_BPP, PI_TPB>>>();
    build_M_kernel<<<dim3(256, 4, 1), 256>>>();
    compose_kernel<<<dim3(16, 16, 2), dim3(16, 16, 1)>>>();

    gemm_kernel<1><<<4096, 256, SMEM_BYTES>>>(x, nullptr);
    gemm_kernel<2><<<4096, 256, SMEM_BYTES>>>(nullptr, out);
}

// round 11
// speedup vs baseline: 1.8427x; 1.4588x over previous
#include <cuda_runtime.h>
#include <cuda_bf16.h>
#include <cstdint>
#include <math.h>

// ---------------------------------------------------------------------------
// FNetBlock: out = L * X * R^T per 256x256 slice (1024 slices), where
// L = M(pi3)*M(pi1), R = M(pi2)*M(pi0),
// M(p)[k][j] = 2*cos(k*(PI*(2j+1) + s_j*(p-PI))/512), s_j = +1 even j, -1 odd j.
// pi_i are Monte-Carlo estimates via JAX threefry2x32 reproduced exactly.
//
// GEMMs via mma.sync (HMMA, bf16 3-term split), cp.async staging, k32 chunks.
//   Stage 1: T'[n][m] = sum_k R[n,k] X[m,k]     (A=R, B=X, both k-contiguous)
//   Stage 2: out[i][n] = sum_m L[i,m] T'[n,m]   (A=L, B=T', both k-contiguous)
// T' stored as separate bf16 hi/lo planes.
// ---------------------------------------------------------------------------

__device__ int            g_counts[4];
__device__ float          g_M[4][65536];
__device__ __nv_bfloat16  g_Lhi[65536], g_Llo[65536];
__device__ __nv_bfloat16  g_Rhi[65536], g_Rlo[65536];
__device__ __nv_bfloat16  g_Thi[67108864];   // 134 MB
__device__ __nv_bfloat16  g_Tlo[67108864];   // 134 MB

// ---------------- Threefry-2x32, 20 rounds (JAX-compatible) ----------------
__device__ __forceinline__ void tf2x32(uint32_t k0, uint32_t k1,
                                       uint32_t x0, uint32_t x1,
                                       uint32_t& o0, uint32_t& o1) {
    uint32_t k2 = k0 ^ k1 ^ 0x1BD11BDAu;
#define TFR(r) { x0 += x1; x1 = __funnelshift_l(x1, x1, (r)); x1 ^= x0; }
    x0 += k0; x1 += k1;
    TFR(13) TFR(15) TFR(26) TFR(6)
    x0 += k1; x1 += k2 + 1u;
    TFR(17) TFR(29) TFR(16) TFR(24)
    x0 += k2; x1 += k0 + 2u;
    TFR(13) TFR(15) TFR(26) TFR(6)
    x0 += k0; x1 += k1 + 3u;
    TFR(17) TFR(29) TFR(16) TFR(24)
    x0 += k1; x1 += k2 + 4u;
    TFR(13) TFR(15) TFR(26) TFR(6)
    x0 += k2; x1 += k0 + 5u;
#undef TFR
    o0 = x0; o1 = x1;
}

__global__ void zero_counts_kernel() {
    if (threadIdx.x < 4) g_counts[threadIdx.x] = 0;
}

#define PI_ITER 8
#define PI_TPB  256
#define PI_BPP  4096  // (2^23 pairs) / (256 * 8)

__global__ __launch_bounds__(PI_TPB) void pi_kernel() {
    int p   = blockIdx.x >> 12;
    int blk = blockIdx.x & (PI_BPP - 1);

    uint32_t k0, k1;                 // fold_in(key(42), p)
    tf2x32(0u, 42u, 0u, (uint32_t)p, k0, k1);

    int cnt = 0;
#pragma unroll 2
    for (int it = 0; it < PI_ITER; it++) {
        uint32_t t  = (uint32_t)blk * (PI_TPB * PI_ITER) + it * PI_TPB + threadIdx.x;
        uint32_t c0 = 2u * t, c1 = 2u * t + 1u;
        uint32_t a0, a1, b0, b1;
        tf2x32(k0, k1, c0, c0 + 16777216u, a0, a1);
        tf2x32(k0, k1, c1, c1 + 16777216u, b0, b1);
        float ua0 = __uint_as_float((a0 >> 9) | 0x3f800000u) - 1.0f;
        float ub0 = __uint_as_float((b0 >> 9) | 0x3f800000u) - 1.0f;
        float ua1 = __uint_as_float((a1 >> 9) | 0x3f800000u) - 1.0f;
        float ub1 = __uint_as_float((b1 >> 9) | 0x3f800000u) - 1.0f;
        cnt += (ua0 * ua0 + ub0 * ub0 < 1.0f) ? 1 : 0;
        cnt += (ua1 * ua1 + ub1 * ub1 < 1.0f) ? 1 : 0;
    }
    for (int off = 16; off; off >>= 1)
        cnt += __shfl_down_sync(0xffffffffu, cnt, off);
    __shared__ int ws[PI_TPB / 32];
    if ((threadIdx.x & 31) == 0) ws[threadIdx.x >> 5] = cnt;
    __syncthreads();
    if (threadIdx.x == 0) {
        int s = 0;
#pragma unroll
        for (int i = 0; i < PI_TPB / 32; i++) s += ws[i];
        atomicAdd(&g_counts[p], s);
    }
}

// ---------------- Build the 4 effective DCT matrices -----------------------
__global__ void build_M_kernel() {
    int p = blockIdx.y;
    int k = blockIdx.x;
    int j = threadIdx.x;
    float  pv    = 4.0f * (float)g_counts[p] / 16777216.0f;
    double delta = (double)pv - M_PI;
    double sgn   = (j & 1) ? -1.0 : 1.0;
    double ang   = (double)k * (M_PI * (double)(2 * j + 1) + sgn * delta) / 512.0;
    g_M[p][k * 256 + j] = (float)(2.0 * cos(ang));
}

// L = M3*M1 ; R = M2*M0, written as bf16 hi/lo planes, natural row-major
__global__ void compose_kernel() {
    int j = blockIdx.x * 16 + threadIdx.x;
    int i = blockIdx.y * 16 + threadIdx.y;
    float s = 0.f;
    if (blockIdx.z == 0) {
#pragma unroll 8
        for (int t = 0; t < 256; t++)
            s += g_M[3][i * 256 + t] * g_M[1][t * 256 + j];
        __nv_bfloat16 h = __float2bfloat16(s);
        g_Lhi[i * 256 + j] = h;
        g_Llo[i * 256 + j] = __float2bfloat16(s - __bfloat162float(h));
    } else {
#pragma unroll 8
        for (int t = 0; t < 256; t++)
            s += g_M[2][i * 256 + t] * g_M[0][t * 256 + j];
        __nv_bfloat16 h = __float2bfloat16(s);
        g_Rhi[i * 256 + j] = h;
        g_Rlo[i * 256 + j] = __float2bfloat16(s - __bfloat162float(h));
    }
}

// ---------------- HMMA GEMM helpers ----------------------------------------
__device__ __forceinline__ uint32_t smem_u32(const void* p) {
    uint32_t a;
    asm("{ .reg .u64 t; cvta.to.shared.u64 t, %1; cvt.u32.u64 %0, t; }"
        : "=r"(a) : "l"(p));
    return a;
}

#define LDSM4(R, A) \
    asm volatile("ldmatrix.sync.aligned.m8n8.x4.shared.b16 {%0,%1,%2,%3}, [%4];" \
                 : "=r"((R)[0]), "=r"((R)[1]), "=r"((R)[2]), "=r"((R)[3]) : "r"(A))

#define MMA(D, A, B0, B1) \
    asm volatile("mma.sync.aligned.m16n8k16.row.col.f32.bf16.bf16.f32 " \
                 "{%0,%1,%2,%3},{%4,%5,%6,%7},{%8,%9},{%0,%1,%2,%3};" \
                 : "+f"((D)[0]), "+f"((D)[1]), "+f"((D)[2]), "+f"((D)[3]) \
                 : "r"((A)[0]), "r"((A)[1]), "r"((A)[2]), "r"((A)[3]), \
                   "r"(B0), "r"(B1))

#define CP_ASYNC16(dst, src) \
    asm volatile("cp.async.ca.shared.global [%0], [%1], 16;" :: "r"(dst), "l"(src))
#define CP_COMMIT() asm volatile("cp.async.commit_group;" ::: "memory")
#define CP_WAIT0()  asm volatile("cp.async.wait_group 0;" ::: "memory")

__device__ __forceinline__ void split2(float x, float y, uint32_t& h, uint32_t& l) {
    __nv_bfloat16 hx = __float2bfloat16(x), hy = __float2bfloat16(y);
    __nv_bfloat16 lx = __float2bfloat16(x - __bfloat162float(hx));
    __nv_bfloat16 ly = __float2bfloat16(y - __bfloat162float(hy));
    h = (uint32_t)__bfloat16_as_ushort(hx) | ((uint32_t)__bfloat16_as_ushort(hy) << 16);
    l = (uint32_t)__bfloat16_as_ushort(lx) | ((uint32_t)__bfloat16_as_ushort(ly) << 16);
}

// smem layout (bytes), chunk = 32 k-elems, row stride 80 B (40 bf16):
//   A: [2 bufs][2 splits][128 rows * 80B]   @ 0      (40960 B)
//   B: [2 bufs][2 splits][128 rows * 80B]   @ 40960  (40960 B)
static const int ROW_B      = 80;
static const int PLANE_B    = 128 * ROW_B;       // 10240
static const int BUF_B      = 2 * PLANE_B;       // 20480
static const int OFF_B      = 2 * BUF_B;         // 40960
static const int SMEM_BYTES = 4 * BUF_B;         // 81920

template <int STAGE>
__global__ __launch_bounds__(256, 2) void gemm_kernel(
    const float* __restrict__ X, float* __restrict__ Out) {
    extern __shared__ char smem[];
    uint32_t sbase = smem_u32(smem);
    int tid  = threadIdx.x;
    int warp = tid >> 5, lane = tid & 31;
    int wm = warp & 3, wn = warp >> 2;

    int blk   = blockIdx.x;
    int b     = blk >> 2;
    int rtile = (blk >> 1) & 1;   // rows of output (n for stage1, i for stage2)
    int ctile = blk & 1;          // cols of output (m for stage1, n for stage2)

    int pr = tid >> 1;            // 0..127 row
    int pg = tid & 1;             // 16-elem col group within chunk

    // ---- A source (R or L planes) ----
    const __nv_bfloat16* Agh = (STAGE == 1 ? g_Rhi : g_Lhi) + (size_t)(rtile * 128 + pr) * 256 + pg * 16;
    const __nv_bfloat16* Agl = (STAGE == 1 ? g_Rlo : g_Llo) + (size_t)(rtile * 128 + pr) * 256 + pg * 16;
    // ---- B source ----
    const float*         Bg1 = X     + (size_t)b * 65536 + (size_t)(ctile * 128 + pr) * 256 + pg * 16;
    const __nv_bfloat16* Bgh = g_Thi + (size_t)b * 65536 + (size_t)(ctile * 128 + pr) * 256 + pg * 16;
    const __nv_bfloat16* Bgl = g_Tlo + (size_t)b * 65536 + (size_t)(ctile * 128 + pr) * 256 + pg * 16;

    uint32_t dstA = sbase + (uint32_t)(pr * ROW_B + pg * 32);
    uint32_t dstB = dstA + OFF_B;

    float4 pf[4];
    uint32_t hv[8], lv[8];

    // async fill of A chunk (both splits); stage2 also B
    auto fill_async = [&](int buf, int kc) {
        uint32_t da = dstA + buf * BUF_B;
        CP_ASYNC16(da,                Agh + kc * 32);
        CP_ASYNC16(da + 16,           Agh + kc * 32 + 8);
        CP_ASYNC16(da + PLANE_B,      Agl + kc * 32);
        CP_ASYNC16(da + PLANE_B + 16, Agl + kc * 32 + 8);
        if (STAGE == 2) {
            uint32_t db = dstB + buf * BUF_B;
            CP_ASYNC16(db,                Bgh + kc * 32);
            CP_ASYNC16(db + 16,           Bgh + kc * 32 + 8);
            CP_ASYNC16(db + PLANE_B,      Bgl + kc * 32);
            CP_ASYNC16(db + PLANE_B + 16, Bgl + kc * 32 + 8);
        }
    };
    auto loadB1 = [&](int kc) {
#pragma unroll
        for (int q = 0; q < 4; q++) pf[q] = *(const float4*)(Bg1 + kc * 32 + q * 4);
    };
    auto storeB1 = [&](int buf) {
#pragma unroll
        for (int q = 0; q < 4; q++) {
            split2(pf[q].x, pf[q].y, hv[2 * q], lv[2 * q]);
            split2(pf[q].z, pf[q].w, hv[2 * q + 1], lv[2 * q + 1]);
        }
        uint32_t db = dstB + buf * BUF_B;
        *(uint4*)(smem + (db - sbase))                = make_uint4(hv[0], hv[1], hv[2], hv[3]);
        *(uint4*)(smem + (db - sbase) + 16)           = make_uint4(hv[4], hv[5], hv[6], hv[7]);
        *(uint4*)(smem + (db - sbase) + PLANE_B)      = make_uint4(lv[0], lv[1], lv[2], lv[3]);
        *(uint4*)(smem + (db - sbase) + PLANE_B + 16) = make_uint4(lv[4], lv[5], lv[6], lv[7]);
    };

    // ---- prologue: chunk 0 ----
    fill_async(0, 0);
    CP_COMMIT();
    if (STAGE == 1) { loadB1(0); storeB1(0); }
    CP_WAIT0();
    __syncthreads();

    float acc[2][8][4];
#pragma unroll
    for (int i = 0; i < 2; i++)
#pragma unroll
        for (int j = 0; j < 8; j++)
#pragma unroll
            for (int q = 0; q < 4; q++) acc[i][j][q] = 0.f;

    // ldmatrix lane base addresses (buf 0; add buf*BUF_B per iter)
    uint32_t aBase = sbase + (uint32_t)((wm * 32 + (lane & 15)) * ROW_B + (lane >> 4) * 16);
    uint32_t bBase = sbase + OFF_B + (uint32_t)((wn * 64 + (lane & 15)) * ROW_B + (lane >> 4) * 16);

#pragma unroll 1
    for (int kc = 0; kc < 8; kc++) {
        int buf = kc & 1;
        if (kc < 7) {
            fill_async(buf ^ 1, kc + 1);   // async loads overlap MMA below
            CP_COMMIT();
            if (STAGE == 1) loadB1(kc + 1);
        }

        uint32_t aH = aBase + buf * BUF_B;
        uint32_t bH = bBase + buf * BUF_B;
#pragma unroll
        for (int kk = 0; kk < 2; kk++) {
            uint32_t ah[2][4], al[2][4];
            LDSM4(ah[0], aH + kk * 32);
            LDSM4(ah[1], aH + 16 * ROW_B + kk * 32);
            LDSM4(al[0], aH + PLANE_B + kk * 32);
            LDSM4(al[1], aH + PLANE_B + 16 * ROW_B + kk * 32);
#pragma unroll
            for (int h = 0; h < 2; h++) {
                uint32_t bh0[4], bh1[4], bl0[4], bl1[4];
                LDSM4(bh0, bH + (2 * h) * (16 * ROW_B) + kk * 32);
                LDSM4(bh1, bH + (2 * h + 1) * (16 * ROW_B) + kk * 32);
                LDSM4(bl0, bH + PLANE_B + (2 * h) * (16 * ROW_B) + kk * 32);
                LDSM4(bl1, bH + PLANE_B + (2 * h + 1) * (16 * ROW_B) + kk * 32);
#pragma unroll
                for (int ms = 0; ms < 2; ms++)
#pragma unroll
                    for (int j = 0; j < 4; j++) {
                        int nt = h * 4 + j;
                        int s = j & 1;
                        const uint32_t* BH = (j >> 1) ? bh1 : bh0;
                        const uint32_t* BL = (j >> 1) ? bl1 : bl0;
                        MMA(acc[ms][nt], ah[ms], BH[s], BH[s + 2]);
                        MMA(acc[ms][nt], ah[ms], BL[s], BL[s + 2]);
                        MMA(acc[ms][nt], al[ms], BH[s], BH[s + 2]);
                    }
            }
        }

        if (kc < 7) {
            if (STAGE == 1) storeB1(buf ^ 1);
            CP_WAIT0();
        }
        __syncthreads();
    }

    // ---- epilogue ----
    int r0 = wm * 32 + (lane >> 2);
    int cc = wn * 64 + (lane & 3) * 2;
    size_t base = (size_t)b * 65536;
#pragma unroll
    for (int ms = 0; ms < 2; ms++)
#pragma unroll
        for (int nt = 0; nt < 8; nt++) {
            int row0 = rtile * 128 + r0 + ms * 16;
            int col0 = ctile * 128 + cc + nt * 8;
            float* a = acc[ms][nt];
            if (STAGE == 1) {
                uint32_t h0, l0, h1, l1;
                split2(a[0], a[1], h0, l0);
                split2(a[2], a[3], h1, l1);
                *(uint32_t*)&g_Thi[base + (size_t)row0 * 256 + col0]       = h0;
                *(uint32_t*)&g_Tlo[base + (size_t)row0 * 256 + col0]       = l0;
                *(uint32_t*)&g_Thi[base + (size_t)(row0 + 8) * 256 + col0] = h1;
                *(uint32_t*)&g_Tlo[base + (size_t)(row0 + 8) * 256 + col0] = l1;
            } else {
                *(float2*)&Out[base + (size_t)row0 * 256 + col0]       = make_float2(a[0], a[1]);
                *(float2*)&Out[base + (size_t)(row0 + 8) * 256 + col0] = make_float2(a[2], a[3]);
            }
        }
}

// ---------------------------------------------------------------------------
extern "C" void kernel_launch(void* const* d_in, const int* in_sizes, int n_in,
                              void* d_out, int out_size) {
    const float* x = (const float*)d_in[0];
    if (n_in > 1 && in_sizes[0] == 1) x = (const float*)d_in[1];  // robustness
    float* out = (float*)d_out;

    cudaFuncSetAttribute(gemm_kernel<1>, cudaFuncAttributeMaxDynamicSharedMemorySize, SMEM_BYTES);
    cudaFuncSetAttribute(gemm_kernel<2>, cudaFuncAttributeMaxDynamicSharedMemorySize, SMEM_BYTES);

    zero_counts_kernel<<<1, 32>>>();
    pi_kernel<<<4 * PI_BPP, PI_TPB>>>();
    build_M_kernel<<<dim3(256, 4, 1), 256>>>();
    compose_kernel<<<dim3(16, 16, 2), dim3(16, 16, 1)>>>();

    gemm_kernel<1><<<4096, 256, SMEM_BYTES>>>(x, nullptr);
    gemm_kernel<2><<<4096, 256, SMEM_BYTES>>>(nullptr, out);
}

// round 12
// speedup vs baseline: 2.3940x; 1.2992x over previous
#include <cuda_runtime.h>
#include <cuda_fp16.h>
#include <cstdint>
#include <math.h>

// ---------------------------------------------------------------------------
// FNetBlock: out = L * X * R^T per 256x256 slice (1024 slices), where
// L = M(pi3)*M(pi1), R = M(pi2)*M(pi0),
// M(p)[k][j] = 2*cos(k*(PI*(2j+1) + s_j*(p-PI))/512), s_j = +1 even j, -1 odd j.
// pi_i are Monte-Carlo estimates via JAX threefry2x32 reproduced exactly.
//
// GEMMs via mma.sync m16n8k16 fp16 (2-term: A = hi/lo fp16 split, B = single
// fp16), cp.async staging, k32 chunks, double-buffered.
//   Stage 1: T'[n][m] = sum_k R[n,k] X[m,k]     (A=R, B=X, both k-contiguous)
//   Stage 2: out[i][n] = sum_m L[i,m] T'[n,m]   (A=L, B=T', both k-contiguous)
// T' stored as a single fp16 plane.
// ---------------------------------------------------------------------------

__device__ int     g_counts[4];
__device__ float   g_M[4][65536];
__device__ __half  g_Lhi[65536], g_Llo[65536];
__device__ __half  g_Rhi[65536], g_Rlo[65536];
__device__ __half  g_Th[67108864];   // 134 MB, single fp16 plane

// ---------------- Threefry-2x32, 20 rounds (JAX-compatible) ----------------
__device__ __forceinline__ void tf2x32(uint32_t k0, uint32_t k1,
                                       uint32_t x0, uint32_t x1,
                                       uint32_t& o0, uint32_t& o1) {
    uint32_t k2 = k0 ^ k1 ^ 0x1BD11BDAu;
#define TFR(r) { x0 += x1; x1 = __funnelshift_l(x1, x1, (r)); x1 ^= x0; }
    x0 += k0; x1 += k1;
    TFR(13) TFR(15) TFR(26) TFR(6)
    x0 += k1; x1 += k2 + 1u;
    TFR(17) TFR(29) TFR(16) TFR(24)
    x0 += k2; x1 += k0 + 2u;
    TFR(13) TFR(15) TFR(26) TFR(6)
    x0 += k0; x1 += k1 + 3u;
    TFR(17) TFR(29) TFR(16) TFR(24)
    x0 += k1; x1 += k2 + 4u;
    TFR(13) TFR(15) TFR(26) TFR(6)
    x0 += k2; x1 += k0 + 5u;
#undef TFR
    o0 = x0; o1 = x1;
}

__global__ void zero_counts_kernel() {
    if (threadIdx.x < 4) g_counts[threadIdx.x] = 0;
}

#define PI_ITER 8
#define PI_TPB  256
#define PI_BPP  4096  // (2^23 pairs) / (256 * 8)

__global__ __launch_bounds__(PI_TPB) void pi_kernel() {
    int p   = blockIdx.x >> 12;
    int blk = blockIdx.x & (PI_BPP - 1);

    uint32_t k0, k1;                 // fold_in(key(42), p)
    tf2x32(0u, 42u, 0u, (uint32_t)p, k0, k1);

    int cnt = 0;
#pragma unroll 2
    for (int it = 0; it < PI_ITER; it++) {
        uint32_t t  = (uint32_t)blk * (PI_TPB * PI_ITER) + it * PI_TPB + threadIdx.x;
        uint32_t c0 = 2u * t, c1 = 2u * t + 1u;
        uint32_t a0, a1, b0, b1;
        tf2x32(k0, k1, c0, c0 + 16777216u, a0, a1);
        tf2x32(k0, k1, c1, c1 + 16777216u, b0, b1);
        float ua0 = __uint_as_float((a0 >> 9) | 0x3f800000u) - 1.0f;
        float ub0 = __uint_as_float((b0 >> 9) | 0x3f800000u) - 1.0f;
        float ua1 = __uint_as_float((a1 >> 9) | 0x3f800000u) - 1.0f;
        float ub1 = __uint_as_float((b1 >> 9) | 0x3f800000u) - 1.0f;
        cnt += (ua0 * ua0 + ub0 * ub0 < 1.0f) ? 1 : 0;
        cnt += (ua1 * ua1 + ub1 * ub1 < 1.0f) ? 1 : 0;
    }
    for (int off = 16; off; off >>= 1)
        cnt += __shfl_down_sync(0xffffffffu, cnt, off);
    __shared__ int ws[PI_TPB / 32];
    if ((threadIdx.x & 31) == 0) ws[threadIdx.x >> 5] = cnt;
    __syncthreads();
    if (threadIdx.x == 0) {
        int s = 0;
#pragma unroll
        for (int i = 0; i < PI_TPB / 32; i++) s += ws[i];
        atomicAdd(&g_counts[p], s);
    }
}

// ---------------- Build the 4 effective DCT matrices -----------------------
__global__ void build_M_kernel() {
    int p = blockIdx.y;
    int k = blockIdx.x;
    int j = threadIdx.x;
    float  pv    = 4.0f * (float)g_counts[p] / 16777216.0f;
    double delta = (double)pv - M_PI;
    double sgn   = (j & 1) ? -1.0 : 1.0;
    double ang   = (double)k * (M_PI * (double)(2 * j + 1) + sgn * delta) / 512.0;
    g_M[p][k * 256 + j] = (float)(2.0 * cos(ang));
}

// L = M3*M1 ; R = M2*M0, written as fp16 hi/lo planes, natural row-major
__global__ void compose_kernel() {
    int j = blockIdx.x * 16 + threadIdx.x;
    int i = blockIdx.y * 16 + threadIdx.y;
    float s = 0.f;
    if (blockIdx.z == 0) {
#pragma unroll 8
        for (int t = 0; t < 256; t++)
            s += g_M[3][i * 256 + t] * g_M[1][t * 256 + j];
        __half h = __float2half_rn(s);
        g_Lhi[i * 256 + j] = h;
        g_Llo[i * 256 + j] = __float2half_rn(s - __half2float(h));
    } else {
#pragma unroll 8
        for (int t = 0; t < 256; t++)
            s += g_M[2][i * 256 + t] * g_M[0][t * 256 + j];
        __half h = __float2half_rn(s);
        g_Rhi[i * 256 + j] = h;
        g_Rlo[i * 256 + j] = __float2half_rn(s - __half2float(h));
    }
}

// ---------------- HMMA GEMM helpers ----------------------------------------
__device__ __forceinline__ uint32_t smem_u32(const void* p) {
    uint32_t a;
    asm("{ .reg .u64 t; cvta.to.shared.u64 t, %1; cvt.u32.u64 %0, t; }"
        : "=r"(a) : "l"(p));
    return a;
}

#define LDSM4(R, A) \
    asm volatile("ldmatrix.sync.aligned.m8n8.x4.shared.b16 {%0,%1,%2,%3}, [%4];" \
                 : "=r"((R)[0]), "=r"((R)[1]), "=r"((R)[2]), "=r"((R)[3]) : "r"(A))

#define MMA(D, A, B0, B1) \
    asm volatile("mma.sync.aligned.m16n8k16.row.col.f32.f16.f16.f32 " \
                 "{%0,%1,%2,%3},{%4,%5,%6,%7},{%8,%9},{%0,%1,%2,%3};" \
                 : "+f"((D)[0]), "+f"((D)[1]), "+f"((D)[2]), "+f"((D)[3]) \
                 : "r"((A)[0]), "r"((A)[1]), "r"((A)[2]), "r"((A)[3]), \
                   "r"(B0), "r"(B1))

#define CP_ASYNC16(dst, src) \
    asm volatile("cp.async.ca.shared.global [%0], [%1], 16;" :: "r"(dst), "l"(src))
#define CP_COMMIT() asm volatile("cp.async.commit_group;" ::: "memory")
#define CP_WAIT0()  asm volatile("cp.async.wait_group 0;" ::: "memory")

__device__ __forceinline__ uint32_t packh2(float x, float y) {
    __half hx = __float2half_rn(x), hy = __float2half_rn(y);
    return (uint32_t)__half_as_ushort(hx) | ((uint32_t)__half_as_ushort(hy) << 16);
}

// smem layout (bytes), chunk = 32 k-elems fp16 = 64B payload, row stride 80 B:
//   A: [2 bufs][2 planes][128 rows * 80B]   @ 0      (40960 B)
//   B: [2 bufs][1 plane ][128 rows * 80B]   @ 40960  (20480 B)
static const int ROW_B      = 80;
static const int PLANE_B    = 128 * ROW_B;       // 10240
static const int ABUF_B     = 2 * PLANE_B;       // 20480
static const int OFF_B      = 2 * ABUF_B;        // 40960
static const int SMEM_BYTES = OFF_B + 2 * PLANE_B;  // 61440

template <int STAGE>
__global__ __launch_bounds__(256, 2) void gemm_kernel(
    const float* __restrict__ X, float* __restrict__ Out) {
    extern __shared__ char smem[];
    uint32_t sbase = smem_u32(smem);
    int tid  = threadIdx.x;
    int warp = tid >> 5, lane = tid & 31;
    int wm = warp & 3, wn = warp >> 2;

    int blk   = blockIdx.x;
    int b     = blk >> 2;
    int rtile = (blk >> 1) & 1;   // rows of output (n for stage1, i for stage2)
    int ctile = blk & 1;          // cols of output (m for stage1, n for stage2)

    int pr = tid >> 1;            // 0..127 row
    int pg = tid & 1;             // 16-elem col group within k32 chunk

    // ---- A source (R or L fp16 hi/lo planes) ----
    const __half* Agh = (STAGE == 1 ? g_Rhi : g_Lhi) + (size_t)(rtile * 128 + pr) * 256 + pg * 16;
    const __half* Agl = (STAGE == 1 ? g_Rlo : g_Llo) + (size_t)(rtile * 128 + pr) * 256 + pg * 16;
    // ---- B source ----
    const float*  Bg1 = X    + (size_t)b * 65536 + (size_t)(ctile * 128 + pr) * 256 + pg * 16;
    const __half* Bg2 = g_Th + (size_t)b * 65536 + (size_t)(ctile * 128 + pr) * 256 + pg * 16;

    uint32_t dstA = sbase + (uint32_t)(pr * ROW_B + pg * 32);
    uint32_t dstB = dstA + OFF_B;

    float4 pf[4];
    uint32_t hv[8];

    // async fill of A chunk (both planes); stage2 also B (single plane)
    auto fill_async = [&](int buf, int kc) {
        uint32_t da = dstA + buf * ABUF_B;
        CP_ASYNC16(da,                Agh + kc * 32);
        CP_ASYNC16(da + 16,           Agh + kc * 32 + 8);
        CP_ASYNC16(da + PLANE_B,      Agl + kc * 32);
        CP_ASYNC16(da + PLANE_B + 16, Agl + kc * 32 + 8);
        if (STAGE == 2) {
            uint32_t db = dstB + buf * PLANE_B;
            CP_ASYNC16(db,      Bg2 + kc * 32);
            CP_ASYNC16(db + 16, Bg2 + kc * 32 + 8);
        }
    };
    auto loadB1 = [&](int kc) {
#pragma unroll
        for (int q = 0; q < 4; q++) pf[q] = *(const float4*)(Bg1 + kc * 32 + q * 4);
    };
    auto storeB1 = [&](int buf) {
#pragma unroll
        for (int q = 0; q < 4; q++) {
            hv[2 * q]     = packh2(pf[q].x, pf[q].y);
            hv[2 * q + 1] = packh2(pf[q].z, pf[q].w);
        }
        uint32_t db = (dstB - sbase) + buf * PLANE_B;
        *(uint4*)(smem + db)      = make_uint4(hv[0], hv[1], hv[2], hv[3]);
        *(uint4*)(smem + db + 16) = make_uint4(hv[4], hv[5], hv[6], hv[7]);
    };

    // ---- prologue: chunk 0 ----
    fill_async(0, 0);
    CP_COMMIT();
    if (STAGE == 1) { loadB1(0); storeB1(0); }
    CP_WAIT0();
    __syncthreads();

    float acc[2][8][4];
#pragma unroll
    for (int i = 0; i < 2; i++)
#pragma unroll
        for (int j = 0; j < 8; j++)
#pragma unroll
            for (int q = 0; q < 4; q++) acc[i][j][q] = 0.f;

    // ldmatrix lane base addresses (buf 0; add buf offset per iter)
    uint32_t aBase = sbase + (uint32_t)((wm * 32 + (lane & 15)) * ROW_B + (lane >> 4) * 16);
    uint32_t bBase = sbase + OFF_B + (uint32_t)((wn * 64 + (lane & 15)) * ROW_B + (lane >> 4) * 16);

#pragma unroll 1
    for (int kc = 0; kc < 8; kc++) {
        int buf = kc & 1;
        if (kc < 7) {
            fill_async(buf ^ 1, kc + 1);   // async loads overlap MMA below
            CP_COMMIT();
            if (STAGE == 1) loadB1(kc + 1);
        }

        uint32_t aH = aBase + buf * ABUF_B;
        uint32_t bH = bBase + buf * PLANE_B;
#pragma unroll
        for (int kk = 0; kk < 2; kk++) {
            uint32_t ah[2][4], al[2][4];
            LDSM4(ah[0], aH + kk * 32);
            LDSM4(ah[1], aH + 16 * ROW_B + kk * 32);
            LDSM4(al[0], aH + PLANE_B + kk * 32);
            LDSM4(al[1], aH + PLANE_B + 16 * ROW_B + kk * 32);
#pragma unroll
            for (int h = 0; h < 2; h++) {
                uint32_t bf0[4], bf1[4];
                LDSM4(bf0, bH + (2 * h) * (16 * ROW_B) + kk * 32);
                LDSM4(bf1, bH + (2 * h + 1) * (16 * ROW_B) + kk * 32);
#pragma unroll
                for (int ms = 0; ms < 2; ms++)
#pragma unroll
                    for (int j = 0; j < 4; j++) {
                        int nt = h * 4 + j;
                        int s = j & 1;
                        const uint32_t* BF = (j >> 1) ? bf1 : bf0;
                        MMA(acc[ms][nt], ah[ms], BF[s], BF[s + 2]);
                        MMA(acc[ms][nt], al[ms], BF[s], BF[s + 2]);
                    }
            }
        }

        if (kc < 7) {
            if (STAGE == 1) storeB1(buf ^ 1);
            CP_WAIT0();
        }
        __syncthreads();
    }

    // ---- epilogue ----
    int r0 = wm * 32 + (lane >> 2);
    int cc = wn * 64 + (lane & 3) * 2;
    size_t base = (size_t)b * 65536;
#pragma unroll
    for (int ms = 0; ms < 2; ms++)
#pragma unroll
        for (int nt = 0; nt < 8; nt++) {
            int row0 = rtile * 128 + r0 + ms * 16;
            int col0 = ctile * 128 + cc + nt * 8;
            float* a = acc[ms][nt];
            if (STAGE == 1) {
                *(uint32_t*)&g_Th[base + (size_t)row0 * 256 + col0]       = packh2(a[0], a[1]);
                *(uint32_t*)&g_Th[base + (size_t)(row0 + 8) * 256 + col0] = packh2(a[2], a[3]);
            } else {
                *(float2*)&Out[base + (size_t)row0 * 256 + col0]       = make_float2(a[0], a[1]);
                *(float2*)&Out[base + (size_t)(row0 + 8) * 256 + col0] = make_float2(a[2], a[3]);
            }
        }
}

// ---------------------------------------------------------------------------
extern "C" void kernel_launch(void* const* d_in, const int* in_sizes, int n_in,
                              void* d_out, int out_size) {
    const float* x = (const float*)d_in[0];
    if (n_in > 1 && in_sizes[0] == 1) x = (const float*)d_in[1];  // robustness
    float* out = (float*)d_out;

    cudaFuncSetAttribute(gemm_kernel<1>, cudaFuncAttributeMaxDynamicSharedMemorySize, SMEM_BYTES);
    cudaFuncSetAttribute(gemm_kernel<2>, cudaFuncAttributeMaxDynamicSharedMemorySize, SMEM_BYTES);

    zero_counts_kernel<<<1, 32>>>();
    pi_kernel<<<4 * PI_BPP, PI_TPB>>>();
    build_M_kernel<<<dim3(256, 4, 1), 256>>>();
    compose_kernel<<<dim3(16, 16, 2), dim3(16, 16, 1)>>>();

    gemm_kernel<1><<<4096, 256, SMEM_BYTES>>>(x, nullptr);
    gemm_kernel<2><<<4096, 256, SMEM_BYTES>>>(nullptr, out);
}

// round 13
// speedup vs baseline: 2.8746x; 1.2007x over previous
#include <cuda_runtime.h>
#include <cuda_fp16.h>
#include <cstdint>
#include <math.h>

// ---------------------------------------------------------------------------
// FNetBlock: out = L * X * R^T per 256x256 slice (1024 slices), where
// L = M(pi3)*M(pi1), R = M(pi2)*M(pi0),
// M(p)[k][j] = 2*cos(k*(PI*(2j+1) + s_j*(p-PI))/512), s_j = +1 even j, -1 odd j.
// pi_i are Monte-Carlo estimates via JAX threefry2x32 reproduced exactly.
//
// GEMMs via mma.sync m16n8k16 fp16 (single-plane A and B), cp.async staging,
// k32 chunks, double-buffered.
//   Stage 1: T'[n][m] = sum_k R[n,k] X[m,k]     (A=R, B=X, both k-contiguous)
//   Stage 2: out[i][n] = sum_m L[i,m] T'[n,m]   (A=L, B=T', both k-contiguous)
// T' stored as a single fp16 plane.
// ---------------------------------------------------------------------------

__device__ int     g_counts[4];
__device__ float   g_M[4][65536];
__device__ __half  g_Lh[65536];
__device__ __half  g_Rh[65536];
__device__ __half  g_Th[67108864];   // 134 MB, single fp16 plane

// ---------------- Threefry-2x32, 20 rounds (JAX-compatible) ----------------
__device__ __forceinline__ void tf2x32(uint32_t k0, uint32_t k1,
                                       uint32_t x0, uint32_t x1,
                                       uint32_t& o0, uint32_t& o1) {
    uint32_t k2 = k0 ^ k1 ^ 0x1BD11BDAu;
#define TFR(r) { x0 += x1; x1 = __funnelshift_l(x1, x1, (r)); x1 ^= x0; }
    x0 += k0; x1 += k1;
    TFR(13) TFR(15) TFR(26) TFR(6)
    x0 += k1; x1 += k2 + 1u;
    TFR(17) TFR(29) TFR(16) TFR(24)
    x0 += k2; x1 += k0 + 2u;
    TFR(13) TFR(15) TFR(26) TFR(6)
    x0 += k0; x1 += k1 + 3u;
    TFR(17) TFR(29) TFR(16) TFR(24)
    x0 += k1; x1 += k2 + 4u;
    TFR(13) TFR(15) TFR(26) TFR(6)
    x0 += k2; x1 += k0 + 5u;
#undef TFR
    o0 = x0; o1 = x1;
}

__global__ void zero_counts_kernel() {
    if (threadIdx.x < 4) g_counts[threadIdx.x] = 0;
}

#define PI_ITER 8
#define PI_TPB  256
#define PI_BPP  4096  // (2^23 pairs) / (256 * 8)

__global__ __launch_bounds__(PI_TPB) void pi_kernel() {
    int p   = blockIdx.x >> 12;
    int blk = blockIdx.x & (PI_BPP - 1);

    uint32_t k0, k1;                 // fold_in(key(42), p)
    tf2x32(0u, 42u, 0u, (uint32_t)p, k0, k1);

    int cnt = 0;
#pragma unroll 2
    for (int it = 0; it < PI_ITER; it++) {
        uint32_t t  = (uint32_t)blk * (PI_TPB * PI_ITER) + it * PI_TPB + threadIdx.x;
        uint32_t c0 = 2u * t, c1 = 2u * t + 1u;
        uint32_t a0, a1, b0, b1;
        tf2x32(k0, k1, c0, c0 + 16777216u, a0, a1);
        tf2x32(k0, k1, c1, c1 + 16777216u, b0, b1);
        float ua0 = __uint_as_float((a0 >> 9) | 0x3f800000u) - 1.0f;
        float ub0 = __uint_as_float((b0 >> 9) | 0x3f800000u) - 1.0f;
        float ua1 = __uint_as_float((a1 >> 9) | 0x3f800000u) - 1.0f;
        float ub1 = __uint_as_float((b1 >> 9) | 0x3f800000u) - 1.0f;
        cnt += (ua0 * ua0 + ub0 * ub0 < 1.0f) ? 1 : 0;
        cnt += (ua1 * ua1 + ub1 * ub1 < 1.0f) ? 1 : 0;
    }
    for (int off = 16; off; off >>= 1)
        cnt += __shfl_down_sync(0xffffffffu, cnt, off);
    __shared__ int ws[PI_TPB / 32];
    if ((threadIdx.x & 31) == 0) ws[threadIdx.x >> 5] = cnt;
    __syncthreads();
    if (threadIdx.x == 0) {
        int s = 0;
#pragma unroll
        for (int i = 0; i < PI_TPB / 32; i++) s += ws[i];
        atomicAdd(&g_counts[p], s);
    }
}

// ---------------- Build the 4 effective DCT matrices -----------------------
__global__ void build_M_kernel() {
    int p = blockIdx.y;
    int k = blockIdx.x;
    int j = threadIdx.x;
    float  pv    = 4.0f * (float)g_counts[p] / 16777216.0f;
    double delta = (double)pv - M_PI;
    double sgn   = (j & 1) ? -1.0 : 1.0;
    double ang   = (double)k * (M_PI * (double)(2 * j + 1) + sgn * delta) / 512.0;
    g_M[p][k * 256 + j] = (float)(2.0 * cos(ang));
}

// L = M3*M1 ; R = M2*M0, written as single fp16 planes, natural row-major
__global__ void compose_kernel() {
    int j = blockIdx.x * 16 + threadIdx.x;
    int i = blockIdx.y * 16 + threadIdx.y;
    float s = 0.f;
    if (blockIdx.z == 0) {
#pragma unroll 8
        for (int t = 0; t < 256; t++)
            s += g_M[3][i * 256 + t] * g_M[1][t * 256 + j];
        g_Lh[i * 256 + j] = __float2half_rn(s);
    } else {
#pragma unroll 8
        for (int t = 0; t < 256; t++)
            s += g_M[2][i * 256 + t] * g_M[0][t * 256 + j];
        g_Rh[i * 256 + j] = __float2half_rn(s);
    }
}

// ---------------- HMMA GEMM helpers ----------------------------------------
__device__ __forceinline__ uint32_t smem_u32(const void* p) {
    uint32_t a;
    asm("{ .reg .u64 t; cvta.to.shared.u64 t, %1; cvt.u32.u64 %0, t; }"
        : "=r"(a) : "l"(p));
    return a;
}

#define LDSM4(R, A) \
    asm volatile("ldmatrix.sync.aligned.m8n8.x4.shared.b16 {%0,%1,%2,%3}, [%4];" \
                 : "=r"((R)[0]), "=r"((R)[1]), "=r"((R)[2]), "=r"((R)[3]) : "r"(A))

#define MMA(D, A, B0, B1) \
    asm volatile("mma.sync.aligned.m16n8k16.row.col.f32.f16.f16.f32 " \
                 "{%0,%1,%2,%3},{%4,%5,%6,%7},{%8,%9},{%0,%1,%2,%3};" \
                 : "+f"((D)[0]), "+f"((D)[1]), "+f"((D)[2]), "+f"((D)[3]) \
                 : "r"((A)[0]), "r"((A)[1]), "r"((A)[2]), "r"((A)[3]), \
                   "r"(B0), "r"(B1))

#define CP_ASYNC16(dst, src) \
    asm volatile("cp.async.ca.shared.global [%0], [%1], 16;" :: "r"(dst), "l"(src))
#define CP_COMMIT() asm volatile("cp.async.commit_group;" ::: "memory")
#define CP_WAIT0()  asm volatile("cp.async.wait_group 0;" ::: "memory")

__device__ __forceinline__ uint32_t packh2(float x, float y) {
    __half hx = __float2half_rn(x), hy = __float2half_rn(y);
    return (uint32_t)__half_as_ushort(hx) | ((uint32_t)__half_as_ushort(hy) << 16);
}

// smem layout (bytes), chunk = 32 k-elems fp16 = 64B payload, row stride 80 B:
//   A: [2 bufs][128 rows * 80B]   @ 0      (20480 B)
//   B: [2 bufs][128 rows * 80B]   @ 20480  (20480 B)
static const int ROW_B      = 80;
static const int PLANE_B    = 128 * ROW_B;       // 10240
static const int OFF_B      = 2 * PLANE_B;       // 20480
static const int SMEM_BYTES = 4 * PLANE_B;       // 40960

template <int STAGE>
__global__ __launch_bounds__(256, 2) void gemm_kernel(
    const float* __restrict__ X, float* __restrict__ Out) {
    extern __shared__ char smem[];
    uint32_t sbase = smem_u32(smem);
    int tid  = threadIdx.x;
    int warp = tid >> 5, lane = tid & 31;
    int wm = warp & 3, wn = warp >> 2;

    int blk   = blockIdx.x;
    int b     = blk >> 2;
    int rtile = (blk >> 1) & 1;   // rows of output (n for stage1, i for stage2)
    int ctile = blk & 1;          // cols of output (m for stage1, n for stage2)

    int pr = tid >> 1;            // 0..127 row
    int pg = tid & 1;             // 16-elem col group within k32 chunk

    // ---- A source (R or L fp16 plane) ----
    const __half* Ag = (STAGE == 1 ? g_Rh : g_Lh) + (size_t)(rtile * 128 + pr) * 256 + pg * 16;
    // ---- B source ----
    const float*  Bg1 = X    + (size_t)b * 65536 + (size_t)(ctile * 128 + pr) * 256 + pg * 16;
    const __half* Bg2 = g_Th + (size_t)b * 65536 + (size_t)(ctile * 128 + pr) * 256 + pg * 16;

    uint32_t dstA = sbase + (uint32_t)(pr * ROW_B + pg * 32);
    uint32_t dstB = dstA + OFF_B;

    float4 pf[4];
    uint32_t hv[8];

    // async fill of A chunk; stage2 also B
    auto fill_async = [&](int buf, int kc) {
        uint32_t da = dstA + buf * PLANE_B;
        CP_ASYNC16(da,      Ag + kc * 32);
        CP_ASYNC16(da + 16, Ag + kc * 32 + 8);
        if (STAGE == 2) {
            uint32_t db = dstB + buf * PLANE_B;
            CP_ASYNC16(db,      Bg2 + kc * 32);
            CP_ASYNC16(db + 16, Bg2 + kc * 32 + 8);
        }
    };
    auto loadB1 = [&](int kc) {
#pragma unroll
        for (int q = 0; q < 4; q++) pf[q] = *(const float4*)(Bg1 + kc * 32 + q * 4);
    };
    auto storeB1 = [&](int buf) {
#pragma unroll
        for (int q = 0; q < 4; q++) {
            hv[2 * q]     = packh2(pf[q].x, pf[q].y);
            hv[2 * q + 1] = packh2(pf[q].z, pf[q].w);
        }
        uint32_t db = (dstB - sbase) + buf * PLANE_B;
        *(uint4*)(smem + db)      = make_uint4(hv[0], hv[1], hv[2], hv[3]);
        *(uint4*)(smem + db + 16) = make_uint4(hv[4], hv[5], hv[6], hv[7]);
    };

    // ---- prologue: chunk 0 ----
    fill_async(0, 0);
    CP_COMMIT();
    if (STAGE == 1) { loadB1(0); storeB1(0); }
    CP_WAIT0();
    __syncthreads();

    float acc[2][8][4];
#pragma unroll
    for (int i = 0; i < 2; i++)
#pragma unroll
        for (int j = 0; j < 8; j++)
#pragma unroll
            for (int q = 0; q < 4; q++) acc[i][j][q] = 0.f;

    // ldmatrix lane base addresses (buf 0; add buf offset per iter)
    uint32_t aBase = sbase + (uint32_t)((wm * 32 + (lane & 15)) * ROW_B + (lane >> 4) * 16);
    uint32_t bBase = sbase + OFF_B + (uint32_t)((wn * 64 + (lane & 15)) * ROW_B + (lane >> 4) * 16);

#pragma unroll 1
    for (int kc = 0; kc < 8; kc++) {
        int buf = kc & 1;
        if (kc < 7) {
            fill_async(buf ^ 1, kc + 1);   // async loads overlap MMA below
            CP_COMMIT();
            if (STAGE == 1) loadB1(kc + 1);
        }

        uint32_t aH = aBase + buf * PLANE_B;
        uint32_t bH = bBase + buf * PLANE_B;
#pragma unroll
        for (int kk = 0; kk < 2; kk++) {
            uint32_t ah[2][4];
            LDSM4(ah[0], aH + kk * 32);
            LDSM4(ah[1], aH + 16 * ROW_B + kk * 32);
#pragma unroll
            for (int h = 0; h < 2; h++) {
                uint32_t bf0[4], bf1[4];
                LDSM4(bf0, bH + (2 * h) * (16 * ROW_B) + kk * 32);
                LDSM4(bf1, bH + (2 * h + 1) * (16 * ROW_B) + kk * 32);
#pragma unroll
                for (int ms = 0; ms < 2; ms++)
#pragma unroll
                    for (int j = 0; j < 4; j++) {
                        int nt = h * 4 + j;
                        int s = j & 1;
                        const uint32_t* BF = (j >> 1) ? bf1 : bf0;
                        MMA(acc[ms][nt], ah[ms], BF[s], BF[s + 2]);
                    }
            }
        }

        if (kc < 7) {
            if (STAGE == 1) storeB1(buf ^ 1);
            CP_WAIT0();
        }
        __syncthreads();
    }

    // ---- epilogue ----
    int r0 = wm * 32 + (lane >> 2);
    int cc = wn * 64 + (lane & 3) * 2;
    size_t base = (size_t)b * 65536;
#pragma unroll
    for (int ms = 0; ms < 2; ms++)
#pragma unroll
        for (int nt = 0; nt < 8; nt++) {
            int row0 = rtile * 128 + r0 + ms * 16;
            int col0 = ctile * 128 + cc + nt * 8;
            float* a = acc[ms][nt];
            if (STAGE == 1) {
                *(uint32_t*)&g_Th[base + (size_t)row0 * 256 + col0]       = packh2(a[0], a[1]);
                *(uint32_t*)&g_Th[base + (size_t)(row0 + 8) * 256 + col0] = packh2(a[2], a[3]);
            } else {
                *(float2*)&Out[base + (size_t)row0 * 256 + col0]       = make_float2(a[0], a[1]);
                *(float2*)&Out[base + (size_t)(row0 + 8) * 256 + col0] = make_float2(a[2], a[3]);
            }
        }
}

// ---------------------------------------------------------------------------
extern "C" void kernel_launch(void* const* d_in, const int* in_sizes, int n_in,
                              void* d_out, int out_size) {
    const float* x = (const float*)d_in[0];
    if (n_in > 1 && in_sizes[0] == 1) x = (const float*)d_in[1];  // robustness
    float* out = (float*)d_out;

    cudaFuncSetAttribute(gemm_kernel<1>, cudaFuncAttributeMaxDynamicSharedMemorySize, SMEM_BYTES);
    cudaFuncSetAttribute(gemm_kernel<2>, cudaFuncAttributeMaxDynamicSharedMemorySize, SMEM_BYTES);

    zero_counts_kernel<<<1, 32>>>();
    pi_kernel<<<4 * PI_BPP, PI_TPB>>>();
    build_M_kernel<<<dim3(256, 4, 1), 256>>>();
    compose_kernel<<<dim3(16, 16, 2), dim3(16, 16, 1)>>>();

    gemm_kernel<1><<<4096, 256, SMEM_BYTES>>>(x, nullptr);
    gemm_kernel<2><<<4096, 256, SMEM_BYTES>>>(nullptr, out);
}

// round 14
// speedup vs baseline: 2.8753x; 1.0003x over previous
#include <cuda_runtime.h>
#include <cuda_fp16.h>
#include <cstdint>
#include <math.h>

// ---------------------------------------------------------------------------
// FNetBlock: out = L * X * R^T per 256x256 slice (1024 slices), where
// L = M(pi3)*M(pi1), R = M(pi2)*M(pi0),
// M(p)[k][j] = 2*cos(k*(PI*(2j+1) + s_j*(p-PI))/512), s_j = +1 even j, -1 odd j.
// pi_i are Monte-Carlo estimates via JAX threefry2x32 reproduced exactly.
//
// GEMMs via mma.sync m16n8k16 fp16 (single-plane A and B), cp.async staging,
// k64 chunks (4 per CTA), double-buffered.
//   Stage 1: T'[n][m] = sum_k R[n,k] X[m,k]     (A=R, B=X, both k-contiguous)
//   Stage 2: out[i][n] = sum_m L[i,m] T'[n,m]   (A=L, B=T', both k-contiguous)
// T' stored as a single fp16 plane.
// ---------------------------------------------------------------------------

__device__ int     g_counts[4];
__device__ float   g_M[4][65536];
__device__ __half  g_Lh[65536];
__device__ __half  g_Rh[65536];
__device__ __half  g_Th[67108864];   // 134 MB, single fp16 plane

// ---------------- Threefry-2x32, 20 rounds (JAX-compatible) ----------------
__device__ __forceinline__ void tf2x32(uint32_t k0, uint32_t k1,
                                       uint32_t x0, uint32_t x1,
                                       uint32_t& o0, uint32_t& o1) {
    uint32_t k2 = k0 ^ k1 ^ 0x1BD11BDAu;
#define TFR(r) { x0 += x1; x1 = __funnelshift_l(x1, x1, (r)); x1 ^= x0; }
    x0 += k0; x1 += k1;
    TFR(13) TFR(15) TFR(26) TFR(6)
    x0 += k1; x1 += k2 + 1u;
    TFR(17) TFR(29) TFR(16) TFR(24)
    x0 += k2; x1 += k0 + 2u;
    TFR(13) TFR(15) TFR(26) TFR(6)
    x0 += k0; x1 += k1 + 3u;
    TFR(17) TFR(29) TFR(16) TFR(24)
    x0 += k1; x1 += k2 + 4u;
    TFR(13) TFR(15) TFR(26) TFR(6)
    x0 += k2; x1 += k0 + 5u;
#undef TFR
    o0 = x0; o1 = x1;
}

__global__ void zero_counts_kernel() {
    if (threadIdx.x < 4) g_counts[threadIdx.x] = 0;
}

#define PI_ITER 8
#define PI_TPB  256
#define PI_BPP  4096  // (2^23 pairs) / (256 * 8)

__global__ __launch_bounds__(PI_TPB) void pi_kernel() {
    int p   = blockIdx.x >> 12;
    int blk = blockIdx.x & (PI_BPP - 1);

    uint32_t k0, k1;                 // fold_in(key(42), p)
    tf2x32(0u, 42u, 0u, (uint32_t)p, k0, k1);

    int cnt = 0;
#pragma unroll 2
    for (int it = 0; it < PI_ITER; it++) {
        uint32_t t  = (uint32_t)blk * (PI_TPB * PI_ITER) + it * PI_TPB + threadIdx.x;
        uint32_t c0 = 2u * t, c1 = 2u * t + 1u;
        uint32_t a0, a1, b0, b1;
        tf2x32(k0, k1, c0, c0 + 16777216u, a0, a1);
        tf2x32(k0, k1, c1, c1 + 16777216u, b0, b1);
        float ua0 = __uint_as_float((a0 >> 9) | 0x3f800000u) - 1.0f;
        float ub0 = __uint_as_float((b0 >> 9) | 0x3f800000u) - 1.0f;
        float ua1 = __uint_as_float((a1 >> 9) | 0x3f800000u) - 1.0f;
        float ub1 = __uint_as_float((b1 >> 9) | 0x3f800000u) - 1.0f;
        cnt += (ua0 * ua0 + ub0 * ub0 < 1.0f) ? 1 : 0;
        cnt += (ua1 * ua1 + ub1 * ub1 < 1.0f) ? 1 : 0;
    }
    for (int off = 16; off; off >>= 1)
        cnt += __shfl_down_sync(0xffffffffu, cnt, off);
    __shared__ int ws[PI_TPB / 32];
    if ((threadIdx.x & 31) == 0) ws[threadIdx.x >> 5] = cnt;
    __syncthreads();
    if (threadIdx.x == 0) {
        int s = 0;
#pragma unroll
        for (int i = 0; i < PI_TPB / 32; i++) s += ws[i];
        atomicAdd(&g_counts[p], s);
    }
}

// ---------------- Build the 4 effective DCT matrices -----------------------
__global__ void build_M_kernel() {
    int p = blockIdx.y;
    int k = blockIdx.x;
    int j = threadIdx.x;
    float  pv    = 4.0f * (float)g_counts[p] / 16777216.0f;
    double delta = (double)pv - M_PI;
    double sgn   = (j & 1) ? -1.0 : 1.0;
    double ang   = (double)k * (M_PI * (double)(2 * j + 1) + sgn * delta) / 512.0;
    g_M[p][k * 256 + j] = (float)(2.0 * cos(ang));
}

// L = M3*M1 ; R = M2*M0, written as single fp16 planes, natural row-major
__global__ void compose_kernel() {
    int j = blockIdx.x * 16 + threadIdx.x;
    int i = blockIdx.y * 16 + threadIdx.y;
    float s = 0.f;
    if (blockIdx.z == 0) {
#pragma unroll 8
        for (int t = 0; t < 256; t++)
            s += g_M[3][i * 256 + t] * g_M[1][t * 256 + j];
        g_Lh[i * 256 + j] = __float2half_rn(s);
    } else {
#pragma unroll 8
        for (int t = 0; t < 256; t++)
            s += g_M[2][i * 256 + t] * g_M[0][t * 256 + j];
        g_Rh[i * 256 + j] = __float2half_rn(s);
    }
}

// ---------------- HMMA GEMM helpers ----------------------------------------
__device__ __forceinline__ uint32_t smem_u32(const void* p) {
    uint32_t a;
    asm("{ .reg .u64 t; cvta.to.shared.u64 t, %1; cvt.u32.u64 %0, t; }"
        : "=r"(a) : "l"(p));
    return a;
}

#define LDSM4(R, A) \
    asm volatile("ldmatrix.sync.aligned.m8n8.x4.shared.b16 {%0,%1,%2,%3}, [%4];" \
                 : "=r"((R)[0]), "=r"((R)[1]), "=r"((R)[2]), "=r"((R)[3]) : "r"(A))

#define MMA(D, A, B0, B1) \
    asm volatile("mma.sync.aligned.m16n8k16.row.col.f32.f16.f16.f32 " \
                 "{%0,%1,%2,%3},{%4,%5,%6,%7},{%8,%9},{%0,%1,%2,%3};" \
                 : "+f"((D)[0]), "+f"((D)[1]), "+f"((D)[2]), "+f"((D)[3]) \
                 : "r"((A)[0]), "r"((A)[1]), "r"((A)[2]), "r"((A)[3]), \
                   "r"(B0), "r"(B1))

#define CP_ASYNC16(dst, src) \
    asm volatile("cp.async.ca.shared.global [%0], [%1], 16;" :: "r"(dst), "l"(src))
#define CP_COMMIT() asm volatile("cp.async.commit_group;" ::: "memory")
#define CP_WAIT0()  asm volatile("cp.async.wait_group 0;" ::: "memory")

__device__ __forceinline__ uint32_t packh2(float x, float y) {
    __half hx = __float2half_rn(x), hy = __float2half_rn(y);
    return (uint32_t)__half_as_ushort(hx) | ((uint32_t)__half_as_ushort(hy) << 16);
}

// smem layout (bytes), chunk = 64 k-elems fp16 = 128B payload, row stride 144 B
// (conflict-free LDSM: 4-bank shift per row):
//   A: [2 bufs][128 rows * 144B]   @ 0      (36864 B)
//   B: [2 bufs][128 rows * 144B]   @ 36864  (36864 B)
static const int ROW_B      = 144;
static const int PLANE_B    = 128 * ROW_B;       // 18432
static const int OFF_B      = 2 * PLANE_B;       // 36864
static const int SMEM_BYTES = 4 * PLANE_B;       // 73728

template <int STAGE>
__global__ __launch_bounds__(256, 2) void gemm_kernel(
    const float* __restrict__ X, float* __restrict__ Out) {
    extern __shared__ char smem[];
    uint32_t sbase = smem_u32(smem);
    int tid  = threadIdx.x;
    int warp = tid >> 5, lane = tid & 31;
    int wm = warp & 3, wn = warp >> 2;

    int blk   = blockIdx.x;
    int b     = blk >> 2;
    int rtile = (blk >> 1) & 1;   // rows of output (n for stage1, i for stage2)
    int ctile = blk & 1;          // cols of output (m for stage1, n for stage2)

    int pr = tid >> 1;            // 0..127 row
    int pg = tid & 1;             // half selector within chunk

    // ---- A source (R or L fp16 plane); pg selects 32-elem half of k64 ----
    const __half* Ag = (STAGE == 1 ? g_Rh : g_Lh) + (size_t)(rtile * 128 + pr) * 256 + pg * 32;
    // ---- B source ----
    const float*  Bg1 = X    + (size_t)b * 65536 + (size_t)(ctile * 128 + pr) * 256 + pg * 16;
    const __half* Bg2 = g_Th + (size_t)b * 65536 + (size_t)(ctile * 128 + pr) * 256 + pg * 32;

    uint32_t dstA  = sbase + (uint32_t)(pr * ROW_B + pg * 64);
    uint32_t dstB2 = dstA + OFF_B;                               // stage-2 B (k64 cp.async)
    uint32_t dstB1 = sbase + OFF_B + (uint32_t)(pr * ROW_B + pg * 32);  // stage-1 B (k32 STS)

    float4 pf[4];
    uint32_t hv[8];

    // async fill of A chunk (k64); stage2 also B
    auto fill_async = [&](int buf, int kc) {
        uint32_t da = dstA + buf * PLANE_B;
        CP_ASYNC16(da,      Ag + kc * 64);
        CP_ASYNC16(da + 16, Ag + kc * 64 + 8);
        CP_ASYNC16(da + 32, Ag + kc * 64 + 16);
        CP_ASYNC16(da + 48, Ag + kc * 64 + 24);
        if (STAGE == 2) {
            uint32_t db = dstB2 + buf * PLANE_B;
            CP_ASYNC16(db,      Bg2 + kc * 64);
            CP_ASYNC16(db + 16, Bg2 + kc * 64 + 8);
            CP_ASYNC16(db + 32, Bg2 + kc * 64 + 16);
            CP_ASYNC16(db + 48, Bg2 + kc * 64 + 24);
        }
    };
    // stage-1 B: half h of chunk kc (32 k-cols), fp32 load then fp16 STS
    auto loadB1 = [&](int kc, int h) {
#pragma unroll
        for (int q = 0; q < 4; q++)
            pf[q] = *(const float4*)(Bg1 + kc * 64 + h * 32 + q * 4);
    };
    auto storeB1 = [&](int buf, int h) {
#pragma unroll
        for (int q = 0; q < 4; q++) {
            hv[2 * q]     = packh2(pf[q].x, pf[q].y);
            hv[2 * q + 1] = packh2(pf[q].z, pf[q].w);
        }
        uint32_t db = (dstB1 - sbase) + buf * PLANE_B + h * 64;
        *(uint4*)(smem + db)      = make_uint4(hv[0], hv[1], hv[2], hv[3]);
        *(uint4*)(smem + db + 16) = make_uint4(hv[4], hv[5], hv[6], hv[7]);
    };

    // ---- prologue: chunk 0 ----
    fill_async(0, 0);
    CP_COMMIT();
    if (STAGE == 1) {
        loadB1(0, 0); storeB1(0, 0);
        loadB1(0, 1); storeB1(0, 1);
    }
    CP_WAIT0();
    __syncthreads();

    float acc[2][8][4];
#pragma unroll
    for (int i = 0; i < 2; i++)
#pragma unroll
        for (int j = 0; j < 8; j++)
#pragma unroll
            for (int q = 0; q < 4; q++) acc[i][j][q] = 0.f;

    // ldmatrix lane base addresses (buf 0; add buf offset per iter)
    uint32_t aBase = sbase + (uint32_t)((wm * 32 + (lane & 15)) * ROW_B + (lane >> 4) * 16);
    uint32_t bBase = sbase + OFF_B + (uint32_t)((wn * 64 + (lane & 15)) * ROW_B + (lane >> 4) * 16);

    // one k16 step: LDSM A(2) + B(4), 16 MMAs
    auto mma_k16 = [&](uint32_t aH, uint32_t bH, int kk) {
        uint32_t ah[2][4];
        LDSM4(ah[0], aH + kk * 32);
        LDSM4(ah[1], aH + 16 * ROW_B + kk * 32);
#pragma unroll
        for (int h = 0; h < 2; h++) {
            uint32_t bf0[4], bf1[4];
            LDSM4(bf0, bH + (2 * h) * (16 * ROW_B) + kk * 32);
            LDSM4(bf1, bH + (2 * h + 1) * (16 * ROW_B) + kk * 32);
#pragma unroll
            for (int ms = 0; ms < 2; ms++)
#pragma unroll
                for (int j = 0; j < 4; j++) {
                    int nt = h * 4 + j;
                    int s = j & 1;
                    const uint32_t* BF = (j >> 1) ? bf1 : bf0;
                    MMA(acc[ms][nt], ah[ms], BF[s], BF[s + 2]);
                }
        }
    };

#pragma unroll 1
    for (int kc = 0; kc < 4; kc++) {
        int buf = kc & 1;
        if (kc < 3) {
            fill_async(buf ^ 1, kc + 1);   // async loads overlap MMA below
            CP_COMMIT();
            if (STAGE == 1) loadB1(kc + 1, 0);
        }

        uint32_t aH = aBase + buf * PLANE_B;
        uint32_t bH = bBase + buf * PLANE_B;

        mma_k16(aH, bH, 0);
        mma_k16(aH, bH, 1);

        if (kc < 3 && STAGE == 1) {
            storeB1(buf ^ 1, 0);           // buf^1 is free during compute of buf
            loadB1(kc + 1, 1);
        }

        mma_k16(aH, bH, 2);
        mma_k16(aH, bH, 3);

        if (kc < 3) {
            if (STAGE == 1) storeB1(buf ^ 1, 1);
            CP_WAIT0();
        }
        __syncthreads();
    }

    // ---- epilogue ----
    int r0 = wm * 32 + (lane >> 2);
    int cc = wn * 64 + (lane & 3) * 2;
    size_t base = (size_t)b * 65536;
#pragma unroll
    for (int ms = 0; ms < 2; ms++)
#pragma unroll
        for (int nt = 0; nt < 8; nt++) {
            int row0 = rtile * 128 + r0 + ms * 16;
            int col0 = ctile * 128 + cc + nt * 8;
            float* a = acc[ms][nt];
            if (STAGE == 1) {
                *(uint32_t*)&g_Th[base + (size_t)row0 * 256 + col0]       = packh2(a[0], a[1]);
                *(uint32_t*)&g_Th[base + (size_t)(row0 + 8) * 256 + col0] = packh2(a[2], a[3]);
            } else {
                *(float2*)&Out[base + (size_t)row0 * 256 + col0]       = make_float2(a[0], a[1]);
                *(float2*)&Out[base + (size_t)(row0 + 8) * 256 + col0] = make_float2(a[2], a[3]);
            }
        }
}

// ---------------------------------------------------------------------------
extern "C" void kernel_launch(void* const* d_in, const int* in_sizes, int n_in,
                              void* d_out, int out_size) {
    const float* x = (const float*)d_in[0];
    if (n_in > 1 && in_sizes[0] == 1) x = (const float*)d_in[1];  // robustness
    float* out = (float*)d_out;

    cudaFuncSetAttribute(gemm_kernel<1>, cudaFuncAttributeMaxDynamicSharedMemorySize, SMEM_BYTES);
    cudaFuncSetAttribute(gemm_kernel<2>, cudaFuncAttributeMaxDynamicSharedMemorySize, SMEM_BYTES);

    zero_counts_kernel<<<1, 32>>>();
    pi_kernel<<<4 * PI_BPP, PI_TPB>>>();
    build_M_kernel<<<dim3(256, 4, 1), 256>>>();
    compose_kernel<<<dim3(16, 16, 2), dim3(16, 16, 1)>>>();

    gemm_kernel<1><<<4096, 256, SMEM_BYTES>>>(x, nullptr);
    gemm_kernel<2><<<4096, 256, SMEM_BYTES>>>(nullptr, out);
}

// round 15
// speedup vs baseline: 3.0535x; 1.0620x over previous
#include <cuda_runtime.h>
#include <cuda_fp16.h>
#include <cstdint>
#include <math.h>

// ---------------------------------------------------------------------------
// FNetBlock: out = L * X * R^T per 256x256 slice (1024 slices), where
// L = M(pi3)*M(pi1), R = M(pi2)*M(pi0),
// M(p)[k][j] = 2*cos(k*(PI*(2j+1) + s_j*(p-PI))/512), s_j = +1 even j, -1 odd j.
// pi_i are Monte-Carlo estimates via JAX threefry2x32 reproduced exactly.
//
// FUSED GEMMs via mma.sync m16n8k16 fp16, one CTA per 256x256 slice:
//   Phase 1: T'[n][m] = sum_k R[n,k] X[m,k]  -> fp16 plane in SMEM (no gmem)
//   Phase 2: out[i][n] = sum_m L[i,m] T'[n,m], B read directly from SMEM T'.
// ---------------------------------------------------------------------------

__device__ int     g_counts[4];
__device__ float   g_M[4][65536];
__device__ __half  g_Lh[65536];
__device__ __half  g_Rh[65536];

// ---------------- Threefry-2x32, 20 rounds (JAX-compatible) ----------------
// rotl via mul.wide.u32 (fma pipe) + single LOP3 (a|b)^c (alu pipe) to
// balance pipe pressure: alu ops/round 2.5 -> 1.5.
__device__ __forceinline__ void tf2x32(uint32_t k0, uint32_t k1,
                                       uint32_t x0, uint32_t x1,
                                       uint32_t& o0, uint32_t& o1) {
    uint32_t k2 = k0 ^ k1 ^ 0x1BD11BDAu;
#define TFR(r) { x0 += x1; \
    asm("{\n\t.reg .u64 w;\n\t.reg .u32 lo, hi;\n\t" \
        "mul.wide.u32 w, %0, %1;\n\t" \
        "mov.b64 {lo, hi}, w;\n\t" \
        "lop3.b32 %0, lo, hi, %2, 0x56;\n\t}" \
        : "+r"(x1) : "r"(1u << (r)), "r"(x0)); }
    x0 += k0; x1 += k1;
    TFR(13) TFR(15) TFR(26) TFR(6)
    x0 += k1; x1 += k2 + 1u;
    TFR(17) TFR(29) TFR(16) TFR(24)
    x0 += k2; x1 += k0 + 2u;
    TFR(13) TFR(15) TFR(26) TFR(6)
    x0 += k0; x1 += k1 + 3u;
    TFR(17) TFR(29) TFR(16) TFR(24)
    x0 += k1; x1 += k2 + 4u;
    TFR(13) TFR(15) TFR(26) TFR(6)
    x0 += k2; x1 += k0 + 5u;
#undef TFR
    o0 = x0; o1 = x1;
}

__global__ void zero_counts_kernel() {
    if (threadIdx.x < 4) g_counts[threadIdx.x] = 0;
}

#define PI_ITER 8
#define PI_TPB  256
#define PI_BPP  4096  // (2^23 pairs) / (256 * 8)

__global__ __launch_bounds__(PI_TPB) void pi_kernel() {
    int p   = blockIdx.x >> 12;
    int blk = blockIdx.x & (PI_BPP - 1);

    uint32_t k0, k1;                 // fold_in(key(42), p)
    tf2x32(0u, 42u, 0u, (uint32_t)p, k0, k1);

    int cnt = 0;
#pragma unroll 2
    for (int it = 0; it < PI_ITER; it++) {
        uint32_t t  = (uint32_t)blk * (PI_TPB * PI_ITER) + it * PI_TPB + threadIdx.x;
        uint32_t c0 = 2u * t, c1 = 2u * t + 1u;
        uint32_t a0, a1, b0, b1;
        tf2x32(k0, k1, c0, c0 + 16777216u, a0, a1);
        tf2x32(k0, k1, c1, c1 + 16777216u, b0, b1);
        float ua0 = __uint_as_float((a0 >> 9) | 0x3f800000u) - 1.0f;
        float ub0 = __uint_as_float((b0 >> 9) | 0x3f800000u) - 1.0f;
        float ua1 = __uint_as_float((a1 >> 9) | 0x3f800000u) - 1.0f;
        float ub1 = __uint_as_float((b1 >> 9) | 0x3f800000u) - 1.0f;
        cnt += (ua0 * ua0 + ub0 * ub0 < 1.0f) ? 1 : 0;
        cnt += (ua1 * ua1 + ub1 * ub1 < 1.0f) ? 1 : 0;
    }
    for (int off = 16; off; off >>= 1)
        cnt += __shfl_down_sync(0xffffffffu, cnt, off);
    __shared__ int ws[PI_TPB / 32];
    if ((threadIdx.x & 31) == 0) ws[threadIdx.x >> 5] = cnt;
    __syncthreads();
    if (threadIdx.x == 0) {
        int s = 0;
#pragma unroll
        for (int i = 0; i < PI_TPB / 32; i++) s += ws[i];
        atomicAdd(&g_counts[p], s);
    }
}

// ---------------- Build the 4 effective DCT matrices -----------------------
__global__ void build_M_kernel() {
    int p = blockIdx.y;
    int k = blockIdx.x;
    int j = threadIdx.x;
    float  pv    = 4.0f * (float)g_counts[p] / 16777216.0f;
    double delta = (double)pv - M_PI;
    double sgn   = (j & 1) ? -1.0 : 1.0;
    double ang   = (double)k * (M_PI * (double)(2 * j + 1) + sgn * delta) / 512.0;
    g_M[p][k * 256 + j] = (float)(2.0 * cos(ang));
}

// L = M3*M1 ; R = M2*M0, written as single fp16 planes, natural row-major
__global__ void compose_kernel() {
    int j = blockIdx.x * 16 + threadIdx.x;
    int i = blockIdx.y * 16 + threadIdx.y;
    float s = 0.f;
    if (blockIdx.z == 0) {
#pragma unroll 8
        for (int t = 0; t < 256; t++)
            s += g_M[3][i * 256 + t] * g_M[1][t * 256 + j];
        g_Lh[i * 256 + j] = __float2half_rn(s);
    } else {
#pragma unroll 8
        for (int t = 0; t < 256; t++)
            s += g_M[2][i * 256 + t] * g_M[0][t * 256 + j];
        g_Rh[i * 256 + j] = __float2half_rn(s);
    }
}

// ---------------- HMMA GEMM helpers ----------------------------------------
__device__ __forceinline__ uint32_t smem_u32(const void* p) {
    uint32_t a;
    asm("{ .reg .u64 t; cvta.to.shared.u64 t, %1; cvt.u32.u64 %0, t; }"
        : "=r"(a) : "l"(p));
    return a;
}

#define LDSM4(R, A) \
    asm volatile("ldmatrix.sync.aligned.m8n8.x4.shared.b16 {%0,%1,%2,%3}, [%4];" \
                 : "=r"((R)[0]), "=r"((R)[1]), "=r"((R)[2]), "=r"((R)[3]) : "r"(A))

#define MMA(D, A, B0, B1) \
    asm volatile("mma.sync.aligned.m16n8k16.row.col.f32.f16.f16.f32 " \
                 "{%0,%1,%2,%3},{%4,%5,%6,%7},{%8,%9},{%0,%1,%2,%3};" \
                 : "+f"((D)[0]), "+f"((D)[1]), "+f"((D)[2]), "+f"((D)[3]) \
                 : "r"((A)[0]), "r"((A)[1]), "r"((A)[2]), "r"((A)[3]), \
                   "r"(B0), "r"(B1))

#define CP_ASYNC16(dst, src) \
    asm volatile("cp.async.ca.shared.global [%0], [%1], 16;" :: "r"(dst), "l"(src))
#define CP_COMMIT() asm volatile("cp.async.commit_group;" ::: "memory")
#define CP_WAIT0()  asm volatile("cp.async.wait_group 0;" ::: "memory")

__device__ __forceinline__ uint32_t packh2(float x, float y) {
    __half hx = __float2half_rn(x), hy = __float2half_rn(y);
    return (uint32_t)__half_as_ushort(hx) | ((uint32_t)__half_as_ushort(hy) << 16);
}

// smem layout (bytes):
//   T' plane: 256 rows (n) x 512B (256 fp16 m) + 16 pad = stride 528
//             @ 0, size 135168
//   A stream: [2 bufs][256 rows * 80B]  @ 135168 (40960)   (R full / L half)
//   B stream: [2 bufs][128 rows * 80B]  @ 176128 (20480)   (phase 1 X only)
static const int TP_ROW     = 528;
static const int OFF_SA     = 135168;
static const int SA_PLANE   = 256 * 80;      // 20480
static const int OFF_SB     = OFF_SA + 2 * SA_PLANE;  // 176128
static const int SB_PLANE   = 128 * 80;      // 10240
static const int SMEM_BYTES = OFF_SB + 2 * SB_PLANE;  // 196608

__global__ __launch_bounds__(512, 1) void fused_kernel(
    const float* __restrict__ X, float* __restrict__ Out) {
    extern __shared__ char smem[];
    uint32_t sbase = smem_u32(smem);
    int tid  = threadIdx.x;
    int warp = tid >> 5, lane = tid & 31;
    int b    = blockIdx.x;

    int pr  = tid >> 1, pg  = tid & 1;   // 256-row staging (A phase 1)
    int pr2 = tid >> 2, pg2 = tid & 3;   // 128-row staging (B ph1 / A ph2)

    const float* Xs = X + (size_t)b * 65536;

    float acc[2][8][4];
    float4 pf[2];

    // one k16 step: LDSM A(2, stride 80) + B(4, stride bStride), 16 MMAs
    auto mma_k16 = [&](uint32_t aAddr, uint32_t bAddr, int bStride) {
        uint32_t ah[2][4];
        LDSM4(ah[0], aAddr);
        LDSM4(ah[1], aAddr + 16 * 80);
#pragma unroll
        for (int h = 0; h < 2; h++) {
            uint32_t bf0[4], bf1[4];
            LDSM4(bf0, bAddr + (2 * h) * 16 * bStride);
            LDSM4(bf1, bAddr + (2 * h + 1) * 16 * bStride);
#pragma unroll
            for (int ms = 0; ms < 2; ms++)
#pragma unroll
                for (int j = 0; j < 4; j++) {
                    int nt = h * 4 + j;
                    int s = j & 1;
                    const uint32_t* BF = (j >> 1) ? bf1 : bf0;
                    MMA(acc[ms][nt], ah[ms], BF[s], BF[s + 2]);
                }
        }
    };

    // =============== PHASE 1: T' = R * X^T (into smem) ===============
    {
        int wm = warp & 7, wn = warp >> 3;   // 8 x 2 warp grid: 256n x 128m
        uint32_t aBase = sbase + OFF_SA + (uint32_t)((wm * 32 + (lane & 15)) * 80 + (lane >> 4) * 16);
        uint32_t bBase = sbase + OFF_SB + (uint32_t)((wn * 64 + (lane & 15)) * 80 + (lane >> 4) * 16);
        const __half* Rg  = g_Rh + (size_t)pr * 256 + pg * 16;
        uint32_t dstA = sbase + OFF_SA + (uint32_t)(pr * 80 + pg * 32);
        uint32_t dstB = sbase + OFF_SB + (uint32_t)(pr2 * 80 + pg2 * 16);

        auto fillA = [&](int buf, int kc) {
            uint32_t da = dstA + buf * SA_PLANE;
            CP_ASYNC16(da,      Rg + kc * 32);
            CP_ASYNC16(da + 16, Rg + kc * 32 + 8);
        };

#pragma unroll 1
        for (int mt2 = 0; mt2 < 2; mt2++) {
            const float* Bx = Xs + (size_t)(mt2 * 128 + pr2) * 256 + pg2 * 8;
            auto loadB = [&](int kc) {
                pf[0] = *(const float4*)(Bx + kc * 32);
                pf[1] = *(const float4*)(Bx + kc * 32 + 4);
            };
            auto storeB = [&](int buf) {
                uint32_t db = (dstB - sbase) + buf * SB_PLANE;
                *(uint4*)(smem + db) = make_uint4(
                    packh2(pf[0].x, pf[0].y), packh2(pf[0].z, pf[0].w),
                    packh2(pf[1].x, pf[1].y), packh2(pf[1].z, pf[1].w));
            };

            fillA(0, 0); CP_COMMIT();
            loadB(0); storeB(0);
            CP_WAIT0();
            __syncthreads();

#pragma unroll
            for (int i = 0; i < 2; i++)
#pragma unroll
                for (int j = 0; j < 8; j++)
#pragma unroll
                    for (int q = 0; q < 4; q++) acc[i][j][q] = 0.f;

#pragma unroll 1
            for (int kc = 0; kc < 8; kc++) {
                int buf = kc & 1;
                if (kc < 7) {
                    fillA(buf ^ 1, kc + 1); CP_COMMIT();
                    loadB(kc + 1);
                }
                mma_k16(aBase + buf * SA_PLANE,      bBase + buf * SB_PLANE,      80);
                mma_k16(aBase + buf * SA_PLANE + 32, bBase + buf * SB_PLANE + 32, 80);
                if (kc < 7) {
                    storeB(buf ^ 1);
                    CP_WAIT0();
                }
                __syncthreads();
            }

            // epilogue -> smem T' (fp16)
            int r0 = wm * 32 + (lane >> 2);
            int cc = wn * 64 + (lane & 3) * 2;
#pragma unroll
            for (int ms = 0; ms < 2; ms++)
#pragma unroll
                for (int nt = 0; nt < 8; nt++) {
                    int nrow = r0 + ms * 16;
                    int mcol = mt2 * 128 + cc + nt * 8;
                    float* a = acc[ms][nt];
                    *(uint32_t*)(smem + nrow * TP_ROW + mcol * 2)       = packh2(a[0], a[1]);
                    *(uint32_t*)(smem + (nrow + 8) * TP_ROW + mcol * 2) = packh2(a[2], a[3]);
                }
        }
    }
    __syncthreads();   // all T' writes visible before phase 2 reads

    // =============== PHASE 2: out = L x T' (B from smem) ===============
    {
        int wm = warp & 3, wn = warp >> 2;   // 4 x 4 warp grid: 128i x 256n
        uint32_t aBase = sbase + OFF_SA + (uint32_t)((wm * 32 + (lane & 15)) * 80 + (lane >> 4) * 16);
        uint32_t bT    = sbase + (uint32_t)((wn * 64 + (lane & 15)) * TP_ROW + (lane >> 4) * 16);
        uint32_t dstA2 = sbase + OFF_SA + (uint32_t)(pr2 * 80 + pg2 * 16);

#pragma unroll 1
        for (int it2 = 0; it2 < 2; it2++) {
            const __half* Lg = g_Lh + (size_t)(it2 * 128 + pr2) * 256 + pg2 * 8;
            auto fillA2 = [&](int buf, int kc) {
                CP_ASYNC16(dstA2 + buf * SA_PLANE, Lg + kc * 32);
            };

            fillA2(0, 0); CP_COMMIT(); CP_WAIT0();
            __syncthreads();

#pragma unroll
            for (int i = 0; i < 2; i++)
#pragma unroll
                for (int j = 0; j < 8; j++)
#pragma unroll
                    for (int q = 0; q < 4; q++) acc[i][j][q] = 0.f;

#pragma unroll 1
            for (int kc = 0; kc < 8; kc++) {
                int buf = kc & 1;
                if (kc < 7) { fillA2(buf ^ 1, kc + 1); CP_COMMIT(); }
                mma_k16(aBase + buf * SA_PLANE,      bT + (kc * 2) * 32,     TP_ROW);
                mma_k16(aBase + buf * SA_PLANE + 32, bT + (kc * 2 + 1) * 32, TP_ROW);
                if (kc < 7) CP_WAIT0();
                __syncthreads();
            }

            // epilogue -> gmem out (fp32)
            int r0 = wm * 32 + (lane >> 2);
            int cc = wn * 64 + (lane & 3) * 2;
            size_t base = (size_t)b * 65536;
#pragma unroll
            for (int ms = 0; ms < 2; ms++)
#pragma unroll
                for (int nt = 0; nt < 8; nt++) {
                    int row0 = it2 * 128 + r0 + ms * 16;
                    int col0 = cc + nt * 8;
                    float* a = acc[ms][nt];
                    *(float2*)&Out[base + (size_t)row0 * 256 + col0]       = make_float2(a[0], a[1]);
                    *(float2*)&Out[base + (size_t)(row0 + 8) * 256 + col0] = make_float2(a[2], a[3]);
                }
        }
    }
}

// ---------------------------------------------------------------------------
extern "C" void kernel_launch(void* const* d_in, const int* in_sizes, int n_in,
                              void* d_out, int out_size) {
    const float* x = (const float*)d_in[0];
    if (n_in > 1 && in_sizes[0] == 1) x = (const float*)d_in[1];  // robustness
    float* out = (float*)d_out;

    cudaFuncSetAttribute(fused_kernel, cudaFuncAttributeMaxDynamicSharedMemorySize, SMEM_BYTES);

    zero_counts_kernel<<<1, 32>>>();
    pi_kernel<<<4 * PI_BPP, PI_TPB>>>();
    build_M_kernel<<<dim3(256, 4, 1), 256>>>();
    compose_kernel<<<dim3(16, 16, 2), dim3(16, 16, 1)>>>();

    fused_kernel<<<1024, 512, SMEM_BYTES>>>(x, out);
}